// round 3
// baseline (speedup 1.0000x reference)
#include <cuda_runtime.h>
#include <math.h>
#include <stdint.h>

#define B_  8
#define TQ_ 1024
#define TK_ 1024
#define D_  1024
#define H_  16
#define HD_ 64

#define SM_PITCH 36            // 36-word pitch -> bank (4*row + k) & 31, conflict-free frags
#define GEMM_SMEM_BYTES (4 * 128 * SM_PITCH * 4 * 2)   // 2 stages x (A+B) x 128x36 words

// ---------------- scratch (static device memory; no allocs allowed) -----------
__device__ float g_q [B_*TQ_*D_];               // q(r) -> Wo-out(exact) -> y(r)
__device__ float g_k [B_*TK_*D_];               // k(r) -> h1(r)
__device__ float g_v [B_*TK_*D_];               // v(r) -> ff(exact)
__device__ float g_sc[134217728];               // scores(exact) -> attn2(r) in place
__device__ float g_ao[B_*TQ_*D_];               // baseR -> ao(r) -> xR
__device__ float g_x [B_*TQ_*D_];               // fusionR -> x(exact)
__device__ float g_w [7*1024*1024];             // rounded weights, 7 slots

// ---------------- tf32 helpers ------------------------------------------------
__device__ __forceinline__ uint32_t f2tf32(float x) {
    uint32_t r;
    asm("cvt.rna.tf32.f32 %0, %1;" : "=r"(r) : "f"(x));
    return r;
}
__device__ __forceinline__ float rtf(float x) {      // round fp32 -> tf32 value
    return __uint_as_float(f2tf32(x));
}

__device__ __forceinline__ void mma_tf32(float* c,
                                         uint32_t a0, uint32_t a1, uint32_t a2, uint32_t a3,
                                         uint32_t b0, uint32_t b1) {
    asm volatile(
        "mma.sync.aligned.m16n8k8.row.col.f32.tf32.tf32.f32 "
        "{%0,%1,%2,%3}, {%4,%5,%6,%7}, {%8,%9}, {%0,%1,%2,%3};"
        : "+f"(c[0]), "+f"(c[1]), "+f"(c[2]), "+f"(c[3])
        : "r"(a0), "r"(a1), "r"(a2), "r"(a3), "r"(b0), "r"(b1));
}

__device__ __forceinline__ void cpa16(uint32_t smem_dst, const float* gsrc) {
    asm volatile("cp.async.cg.shared.global [%0], [%1], 16;"
                 :: "r"(smem_dst), "l"(gsrc));
}
__device__ __forceinline__ uint32_t smem_u32(const void* p) {
    uint32_t a;
    asm("{ .reg .u64 t; cvta.to.shared.u64 t, %1; cvt.u32.u64 %0, t; }" : "=r"(a) : "l"(p));
    return a;
}

// ---------------- reductions --------------------------------------------------
__device__ __forceinline__ float warpRedMax(float v) {
#pragma unroll
    for (int o = 16; o > 0; o >>= 1) v = fmaxf(v, __shfl_xor_sync(0xffffffffu, v, o));
    return v;
}
__device__ __forceinline__ float warpRedSum(float v) {
#pragma unroll
    for (int o = 16; o > 0; o >>= 1) v += __shfl_xor_sync(0xffffffffu, v, o);
    return v;
}
__device__ __forceinline__ float blockRedMax(float v, float* red) {
    v = warpRedMax(v);
    if ((threadIdx.x & 31) == 0) red[threadIdx.x >> 5] = v;
    __syncthreads();
    if (threadIdx.x < 32) {
        float x = (threadIdx.x < (blockDim.x >> 5)) ? red[threadIdx.x] : -3.4e38f;
        x = warpRedMax(x);
        if (threadIdx.x == 0) red[0] = x;
    }
    __syncthreads();
    float r = red[0];
    __syncthreads();
    return r;
}
__device__ __forceinline__ float blockRedSum(float v, float* red) {
    v = warpRedSum(v);
    if ((threadIdx.x & 31) == 0) red[threadIdx.x >> 5] = v;
    __syncthreads();
    if (threadIdx.x < 32) {
        float x = (threadIdx.x < (blockDim.x >> 5)) ? red[threadIdx.x] : 0.f;
        x = warpRedSum(x);
        if (threadIdx.x == 0) red[0] = x;
    }
    __syncthreads();
    float r = red[0];
    __syncthreads();
    return r;
}

// ---------------- tf32 pre-round copy -----------------------------------------
__global__ void __launch_bounds__(256)
round_tf32_k(const float* __restrict__ in, float* __restrict__ out, int n4)
{
    int i = blockIdx.x * 256 + threadIdx.x;
    if (i < n4) {
        float4 v = reinterpret_cast<const float4*>(in)[i];
        v.x = rtf(v.x); v.y = rtf(v.y); v.z = rtf(v.z); v.w = rtf(v.w);
        reinterpret_cast<float4*>(out)[i] = v;
    }
}

// ============ TF32 GEMM: C = alpha * A @ B^T (+bias)(+silu)(+round) ===========
// Inputs MUST be pre-rounded to tf32 (low 13 mantissa bits zero).
// A:[M,K] lda, B:[N,K] ldb, C:[M,N] ldc. Block 128x128x32, 256 thr, cp.async
// 2-stage pipeline. mode bits: 1=bias, 2=silu, 4=round output to tf32.
__global__ void __launch_bounds__(256, 2)
gemm_nt_tf32(const float* __restrict__ A, const float* __restrict__ Bm,
             float* __restrict__ C, int Kd, int lda, int ldb, int ldc,
             long sA1, long sA2, long sB1, long sB2, long sC1, long sC2,
             float alpha, const float* __restrict__ bias, int mode)
{
    extern __shared__ uint32_t smbuf[];
    uint32_t* As = smbuf;                         // [2][128][36]
    uint32_t* Bs = smbuf + 2 * 128 * SM_PITCH;    // [2][128][36]
    const uint32_t aBase = smem_u32(As);
    const uint32_t bBase = smem_u32(Bs);

    const int z = blockIdx.z;
    const long zb = z >> 4, zh = z & 15;
    const float* Ab = A  + zb * sA1 + zh * sA2;
    const float* Bb = Bm + zb * sB1 + zh * sB2;
    float*       Cb = C  + zb * sC1 + zh * sC2;

    const int tid   = threadIdx.x;
    const int m0    = blockIdx.y * 128;
    const int n0    = blockIdx.x * 128;
    const int warp  = tid >> 5;
    const int lane  = tid & 31;
    const int warpM = warp & 1;
    const int warpN = warp >> 1;
    const int g     = lane >> 2;
    const int tg    = lane & 3;

    const int lr = tid >> 3;         // 0..31
    const int lc = (tid & 7) * 4;    // 0..28

    float acc[4][4][4];
#pragma unroll
    for (int mt = 0; mt < 4; mt++)
#pragma unroll
        for (int nt = 0; nt < 4; nt++)
#pragma unroll
            for (int r = 0; r < 4; r++) acc[mt][nt][r] = 0.f;

    // prefetch stage 0
#pragma unroll
    for (int i = 0; i < 4; i++) {
        const int r = lr + i * 32;
        cpa16(aBase + (uint32_t)((r * SM_PITCH + lc) * 4),
              &Ab[(long)(m0 + r) * lda + lc]);
        cpa16(bBase + (uint32_t)((r * SM_PITCH + lc) * 4),
              &Bb[(long)(n0 + r) * ldb + lc]);
    }
    asm volatile("cp.async.commit_group;");

    for (int k0 = 0; k0 < Kd; k0 += 32) {
        const int st = (k0 >> 5) & 1;
        if (k0 + 32 < Kd) {
            const int sn = st ^ 1;
            const uint32_t aOff = aBase + (uint32_t)(sn * 128 * SM_PITCH * 4);
            const uint32_t bOff = bBase + (uint32_t)(sn * 128 * SM_PITCH * 4);
#pragma unroll
            for (int i = 0; i < 4; i++) {
                const int r = lr + i * 32;
                cpa16(aOff + (uint32_t)((r * SM_PITCH + lc) * 4),
                      &Ab[(long)(m0 + r) * lda + k0 + 32 + lc]);
                cpa16(bOff + (uint32_t)((r * SM_PITCH + lc) * 4),
                      &Bb[(long)(n0 + r) * ldb + k0 + 32 + lc]);
            }
        }
        asm volatile("cp.async.commit_group;");
        asm volatile("cp.async.wait_group 1;");
        __syncthreads();

        const uint32_t* Ast = As + st * 128 * SM_PITCH;
        const uint32_t* Bst = Bs + st * 128 * SM_PITCH;
#pragma unroll
        for (int kk = 0; kk < 32; kk += 8) {
            uint32_t af[4][4], bf[4][2];
#pragma unroll
            for (int mt = 0; mt < 4; mt++) {
                const int row = warpM * 64 + mt * 16 + g;
                af[mt][0] = Ast[row * SM_PITCH + kk + tg];
                af[mt][1] = Ast[(row + 8) * SM_PITCH + kk + tg];
                af[mt][2] = Ast[row * SM_PITCH + kk + tg + 4];
                af[mt][3] = Ast[(row + 8) * SM_PITCH + kk + tg + 4];
            }
#pragma unroll
            for (int nt = 0; nt < 4; nt++) {
                const int col = warpN * 32 + nt * 8 + g;
                bf[nt][0] = Bst[col * SM_PITCH + kk + tg];
                bf[nt][1] = Bst[col * SM_PITCH + kk + tg + 4];
            }
#pragma unroll
            for (int mt = 0; mt < 4; mt++)
#pragma unroll
                for (int nt = 0; nt < 4; nt++)
                    mma_tf32(acc[mt][nt], af[mt][0], af[mt][1], af[mt][2], af[mt][3],
                             bf[nt][0], bf[nt][1]);
        }
        __syncthreads();
    }

#pragma unroll
    for (int mt = 0; mt < 4; mt++) {
#pragma unroll
        for (int nt = 0; nt < 4; nt++) {
            const long row = m0 + warpM * 64 + mt * 16 + g;
            const int  col = n0 + warpN * 32 + nt * 8 + 2 * tg;
            float v0 = acc[mt][nt][0] * alpha;
            float v1 = acc[mt][nt][1] * alpha;
            float v2 = acc[mt][nt][2] * alpha;
            float v3 = acc[mt][nt][3] * alpha;
            if (mode & 1) {
                const float bb0 = bias[col], bb1 = bias[col + 1];
                v0 += bb0; v1 += bb1; v2 += bb0; v3 += bb1;
            }
            if (mode & 2) {
                v0 = v0 / (1.f + expf(-v0));
                v1 = v1 / (1.f + expf(-v1));
                v2 = v2 / (1.f + expf(-v2));
                v3 = v3 / (1.f + expf(-v3));
            }
            if (mode & 4) {
                v0 = rtf(v0); v1 = rtf(v1); v2 = rtf(v2); v3 = rtf(v3);
            }
            *reinterpret_cast<float2*>(&Cb[row * ldc + col])       = make_float2(v0, v1);
            *reinterpret_cast<float2*>(&Cb[(row + 8) * ldc + col]) = make_float2(v2, v3);
        }
    }
}

// ============ TF32 attn2 @ V (NN, N=64, per (b,h)) ============================
// Inputs pre-rounded; output rounded (feeds Wo GEMM only).
__global__ void __launch_bounds__(256)
attn_v_tf32(const float* __restrict__ A2, const float* __restrict__ Vp,
            float* __restrict__ Cout)
{
    const int z  = blockIdx.z;
    const long zb = z >> 4, zh = z & 15;
    const float* Ab = A2 + (long)z * ((long)TQ_ * TK_);
    const float* Bb = Vp + zb * ((long)TK_ * D_) + zh * HD_;
    float*       Cb = Cout + zb * ((long)TQ_ * D_) + zh * HD_;
    const int m0 = blockIdx.y * 128;

    __shared__ uint32_t As[128][SM_PITCH];
    __shared__ uint32_t Bs[64][SM_PITCH];

    const int tid   = threadIdx.x;
    const int warp  = tid >> 5;
    const int lane  = tid & 31;
    const int warpM = warp & 3;
    const int warpN = warp >> 2;
    const int g     = lane >> 2;
    const int tg    = lane & 3;

    const int lr = tid >> 3;
    const int lc = (tid & 7) * 4;

    float acc[2][4][4];
#pragma unroll
    for (int mt = 0; mt < 2; mt++)
#pragma unroll
        for (int nt = 0; nt < 4; nt++)
#pragma unroll
            for (int r = 0; r < 4; r++) acc[mt][nt][r] = 0.f;

    for (int k0 = 0; k0 < TK_; k0 += 32) {
#pragma unroll
        for (int i = 0; i < 4; i++) {
            const int r = lr + i * 32;
            float4 av = *reinterpret_cast<const float4*>(&Ab[(long)(m0 + r) * TK_ + k0 + lc]);
            As[r][lc + 0] = __float_as_uint(av.x); As[r][lc + 1] = __float_as_uint(av.y);
            As[r][lc + 2] = __float_as_uint(av.z); As[r][lc + 3] = __float_as_uint(av.w);
        }
#pragma unroll
        for (int i = 0; i < 2; i++) {
            const int k = (tid >> 4) + i * 16;
            const int c = (tid & 15) * 4;
            float4 vv = *reinterpret_cast<const float4*>(&Bb[(long)(k0 + k) * D_ + c]);
            Bs[c + 0][k] = __float_as_uint(vv.x); Bs[c + 1][k] = __float_as_uint(vv.y);
            Bs[c + 2][k] = __float_as_uint(vv.z); Bs[c + 3][k] = __float_as_uint(vv.w);
        }
        __syncthreads();

#pragma unroll
        for (int kk = 0; kk < 32; kk += 8) {
            uint32_t af[2][4], bf[4][2];
#pragma unroll
            for (int mt = 0; mt < 2; mt++) {
                const int row = warpM * 32 + mt * 16 + g;
                af[mt][0] = As[row    ][kk + tg];
                af[mt][1] = As[row + 8][kk + tg];
                af[mt][2] = As[row    ][kk + tg + 4];
                af[mt][3] = As[row + 8][kk + tg + 4];
            }
#pragma unroll
            for (int nt = 0; nt < 4; nt++) {
                const int col = warpN * 32 + nt * 8 + g;
                bf[nt][0] = Bs[col][kk + tg];
                bf[nt][1] = Bs[col][kk + tg + 4];
            }
#pragma unroll
            for (int mt = 0; mt < 2; mt++)
#pragma unroll
                for (int nt = 0; nt < 4; nt++)
                    mma_tf32(acc[mt][nt], af[mt][0], af[mt][1], af[mt][2], af[mt][3],
                             bf[nt][0], bf[nt][1]);
        }
        __syncthreads();
    }

#pragma unroll
    for (int mt = 0; mt < 2; mt++) {
#pragma unroll
        for (int nt = 0; nt < 4; nt++) {
            const long row = m0 + warpM * 32 + mt * 16 + g;
            const int  col = warpN * 32 + nt * 8 + 2 * tg;
            *reinterpret_cast<float2*>(&Cb[row * D_ + col]) =
                make_float2(rtf(acc[mt][nt][0]), rtf(acc[mt][nt][1]));
            *reinterpret_cast<float2*>(&Cb[(row + 8) * D_ + col]) =
                make_float2(rtf(acc[mt][nt][2]), rtf(acc[mt][nt][3]));
        }
    }
}

// ---------------- softmax -> mask -> softmax2 ---------------------------------
// masked written exact; attn2 written tf32-rounded (feeds attn_v GEMM).
__global__ void __launch_bounds__(256)
softmax_mask_k(float* __restrict__ scores, float* __restrict__ masked,
               const float* __restrict__ alphap)
{
    __shared__ float red[32];
    const long row = blockIdx.x;
    float4* srow = reinterpret_cast<float4*>(scores + row * 1024);
    float4* mrow = reinterpret_cast<float4*>(masked + row * 1024);
    const int tid = threadIdx.x;
    const float alpha = *alphap;

    float4 v4 = srow[tid];
    float v[4] = {v4.x, v4.y, v4.z, v4.w};

    float mx = fmaxf(fmaxf(v[0], v[1]), fmaxf(v[2], v[3]));
    mx = blockRedMax(mx, red);

    float e[4], s = 0.f;
#pragma unroll
    for (int i = 0; i < 4; i++) { e[i] = expf(v[i] - mx); s += e[i]; }
    s = blockRedSum(s, red);
    const float inv = 1.f / s;

    float mk[4];
#pragma unroll
    for (int i = 0; i < 4; i++) {
        float a = e[i] * inv;
        mk[i] = (a >= alpha) ? a : 0.f;
    }
    mrow[tid] = make_float4(mk[0], mk[1], mk[2], mk[3]);

    float mx2 = fmaxf(fmaxf(mk[0], mk[1]), fmaxf(mk[2], mk[3]));
    mx2 = blockRedMax(mx2, red);

    float e2[4], s2 = 0.f;
#pragma unroll
    for (int i = 0; i < 4; i++) { e2[i] = expf(mk[i] - mx2); s2 += e2[i]; }
    s2 = blockRedSum(s2, red);
    const float inv2 = 1.f / s2;

    srow[tid] = make_float4(rtf(e2[0] * inv2), rtf(e2[1] * inv2),
                            rtf(e2[2] * inv2), rtf(e2[3] * inv2));
}

// ---------------- out = LayerNorm(a + b) * g + beta ---------------------------
// roundMain: round the primary output. out_r (optional): extra rounded copy.
__global__ void __launch_bounds__(256)
add_ln_k(const float* __restrict__ A, const float* __restrict__ Bsrc,
         const float* __restrict__ g, const float* __restrict__ bet,
         float* __restrict__ out, float* __restrict__ out_r, int roundMain)
{
    __shared__ float red[32];
    const long row = blockIdx.x;
    const int tid = threadIdx.x;

    float4 a4 = reinterpret_cast<const float4*>(A    + row * 1024)[tid];
    float4 b4 = reinterpret_cast<const float4*>(Bsrc + row * 1024)[tid];
    float x[4] = {a4.x + b4.x, a4.y + b4.y, a4.z + b4.z, a4.w + b4.w};

    float s = x[0] + x[1] + x[2] + x[3];
    s = blockRedSum(s, red);
    const float mu = s * (1.f / 1024.f);

    float vs = 0.f;
#pragma unroll
    for (int i = 0; i < 4; i++) { float d = x[i] - mu; vs += d * d; }
    vs = blockRedSum(vs, red);
    const float inv = rsqrtf(vs * (1.f / 1024.f) + 1e-5f);

    float4 g4 = reinterpret_cast<const float4*>(g)[tid];
    float4 e4 = reinterpret_cast<const float4*>(bet)[tid];
    float o[4];
    o[0] = (x[0] - mu) * inv * g4.x + e4.x;
    o[1] = (x[1] - mu) * inv * g4.y + e4.y;
    o[2] = (x[2] - mu) * inv * g4.z + e4.z;
    o[3] = (x[3] - mu) * inv * g4.w + e4.w;

    float4 om;
    if (roundMain) om = make_float4(rtf(o[0]), rtf(o[1]), rtf(o[2]), rtf(o[3]));
    else           om = make_float4(o[0], o[1], o[2], o[3]);
    reinterpret_cast<float4*>(out + row * 1024)[tid] = om;
    if (out_r)
        reinterpret_cast<float4*>(out_r + row * 1024)[tid] =
            make_float4(rtf(o[0]), rtf(o[1]), rtf(o[2]), rtf(o[3]));
}

// ---------------- driver ------------------------------------------------------
extern "C" void kernel_launch(void* const* d_in, const int* in_sizes, int n_in,
                              void* d_out, int out_size)
{
    const float* base   = (const float*)d_in[0];
    const float* fusion = (const float*)d_in[1];
    const float* Wq     = (const float*)d_in[2];
    const float* Wk     = (const float*)d_in[3];
    const float* Wv     = (const float*)d_in[4];
    const float* Wo     = (const float*)d_in[5];
    const float* g1     = (const float*)d_in[6];
    const float* b1     = (const float*)d_in[7];
    const float* g2     = (const float*)d_in[8];
    const float* b2     = (const float*)d_in[9];
    const float* fc1_w  = (const float*)d_in[10];
    const float* fc1_b  = (const float*)d_in[11];
    const float* fc2_w  = (const float*)d_in[12];
    const float* fc2_b  = (const float*)d_in[13];
    const float* rw     = (const float*)d_in[14];
    const float* rbias  = (const float*)d_in[15];
    const float* alphap = (const float*)d_in[16];

    float* outf = (float*)d_out;                       // final [8,1024,1024]
    float* outm = outf + (long)B_ * TQ_ * D_;          // masked [8,16,1024,1024]

    float *q, *k, *v, *sc, *ao, *x, *w;
    cudaGetSymbolAddress((void**)&q,  g_q);
    cudaGetSymbolAddress((void**)&k,  g_k);
    cudaGetSymbolAddress((void**)&v,  g_v);
    cudaGetSymbolAddress((void**)&sc, g_sc);
    cudaGetSymbolAddress((void**)&ao, g_ao);
    cudaGetSymbolAddress((void**)&x,  g_x);
    cudaGetSymbolAddress((void**)&w,  g_w);

    cudaFuncSetAttribute(gemm_nt_tf32,
                         cudaFuncAttributeMaxDynamicSharedMemorySize, GEMM_SMEM_BYTES);

    const dim3 blk(256);
    const dim3 gBig(D_ / 128, (B_ * TQ_) / 128, 1);
    const int WN = 1024 * 1024;                        // weight elems
    const int act4 = (B_ * TQ_ * D_) / 4;
    const int w4 = WN / 4;
    const int RB = 256;

    // pre-round external GEMM inputs to tf32
    round_tf32_k<<<(act4 + RB - 1) / RB, RB>>>(base,   ao, act4);   // baseR -> g_ao
    round_tf32_k<<<(act4 + RB - 1) / RB, RB>>>(fusion, x,  act4);   // fusionR -> g_x
    const float* Ws[7] = {Wq, Wk, Wv, Wo, fc1_w, fc2_w, rw};
    for (int i = 0; i < 7; i++)
        round_tf32_k<<<(w4 + RB - 1) / RB, RB>>>(Ws[i], w + (long)i * WN, w4);
    const float *WqR = w, *WkR = w + WN, *WvR = w + 2L*WN, *WoR = w + 3L*WN,
                *f1R = w + 4L*WN, *f2R = w + 5L*WN, *rwR = w + 6L*WN;

    // Q/K/V projections (outputs rounded: feed GEMMs only)
    gemm_nt_tf32<<<gBig, blk, GEMM_SMEM_BYTES>>>(ao, WqR, q, D_, D_, D_, D_, 0,0,0,0,0,0, 1.f, nullptr, 4);
    gemm_nt_tf32<<<gBig, blk, GEMM_SMEM_BYTES>>>(x,  WkR, k, D_, D_, D_, D_, 0,0,0,0,0,0, 1.f, nullptr, 4);
    gemm_nt_tf32<<<gBig, blk, GEMM_SMEM_BYTES>>>(x,  WvR, v, D_, D_, D_, D_, 0,0,0,0,0,0, 1.f, nullptr, 4);

    // scores = Q K^T / 8 (exact output -> softmax)
    gemm_nt_tf32<<<dim3(TK_ / 128, TQ_ / 128, B_ * H_), blk, GEMM_SMEM_BYTES>>>(
        q, k, sc, HD_, D_, D_, TK_,
        (long)TQ_ * D_, HD_, (long)TK_ * D_, HD_,
        (long)H_ * TQ_ * TK_, (long)TQ_ * TK_,
        0.125f, nullptr, 0);

    // softmax -> masked (exact) -> attn2 (rounded, in place)
    softmax_mask_k<<<B_ * H_ * TQ_, blk>>>(sc, outm, alphap);

    // attn2 @ V -> ao (rounded)
    attn_v_tf32<<<dim3(1, TQ_ / 128, B_ * H_), blk>>>(sc, v, ao);

    // O projection (exact -> LN1)
    gemm_nt_tf32<<<gBig, blk, GEMM_SMEM_BYTES>>>(ao, WoR, q, D_, D_, D_, D_, 0,0,0,0,0,0, 1.f, nullptr, 0);

    // x = LN(base + proj): exact -> g_x, rounded copy -> g_ao
    add_ln_k<<<B_ * TQ_, blk>>>(base, q, g1, b1, x, ao, 0);

    // FFN: h1 = silu(xR fc1^T + b) rounded; ff = silu(h1 fc2^T + b) exact
    gemm_nt_tf32<<<gBig, blk, GEMM_SMEM_BYTES>>>(ao, f1R, k, D_, D_, D_, D_, 0,0,0,0,0,0, 1.f, fc1_b, 7);
    gemm_nt_tf32<<<gBig, blk, GEMM_SMEM_BYTES>>>(k,  f2R, v, D_, D_, D_, D_, 0,0,0,0,0,0, 1.f, fc2_b, 3);

    // y = LN(x + ff) rounded (feeds rw GEMM only)
    add_ln_k<<<B_ * TQ_, blk>>>(x, v, g2, b2, q, nullptr, 1);

    // final = y rw^T + rb (exact output)
    gemm_nt_tf32<<<gBig, blk, GEMM_SMEM_BYTES>>>(q, rwR, outf, D_, D_, D_, D_, 0,0,0,0,0,0, 1.f, rbias, 1);
}

// round 5
// speedup vs baseline: 1.1486x; 1.1486x over previous
#include <cuda_runtime.h>
#include <math.h>
#include <stdint.h>

#define B_  8
#define TQ_ 1024
#define TK_ 1024
#define D_  1024
#define H_  16
#define HD_ 64

#define SM_PITCH 36            // words; bank(row r, word k) = (4r + k) & 31
#define STAGE_WORDS (128 * SM_PITCH)                 // one 128x32 tile (padded)
#define GEMM_SMEM_BYTES (2 * 2 * STAGE_WORDS * 4)    // 2 stages x (A+B) = 73728 B

// ---------------- scratch (static device memory; no allocs allowed) -----------
__device__ float g_q [B_*TQ_*D_];
__device__ float g_k [B_*TK_*D_];
__device__ float g_v [B_*TK_*D_];
__device__ float g_sc[134217728];
__device__ float g_ao[B_*TQ_*D_];
__device__ float g_x [B_*TQ_*D_];
__device__ float g_w [7*1024*1024];

// ---------------- helpers ------------------------------------------------------
__device__ __forceinline__ uint32_t f2tf32(float x) {
    uint32_t r;
    asm("cvt.rna.tf32.f32 %0, %1;" : "=r"(r) : "f"(x));
    return r;
}
__device__ __forceinline__ float rtf(float x) { return __uint_as_float(f2tf32(x)); }

__device__ __forceinline__ void mma_tf32(float* c,
                                         uint32_t a0, uint32_t a1, uint32_t a2, uint32_t a3,
                                         uint32_t b0, uint32_t b1) {
    asm volatile(
        "mma.sync.aligned.m16n8k8.row.col.f32.tf32.tf32.f32 "
        "{%0,%1,%2,%3}, {%4,%5,%6,%7}, {%8,%9}, {%0,%1,%2,%3};"
        : "+f"(c[0]), "+f"(c[1]), "+f"(c[2]), "+f"(c[3])
        : "r"(a0), "r"(a1), "r"(a2), "r"(a3), "r"(b0), "r"(b1));
}

// ldmatrix x4 (b16 view): 4 8x8-b16 mats == 4 (8rows x 4cols) tf32 mats.
__device__ __forceinline__ void ldmx4(uint32_t* r, uint32_t addr) {
    asm volatile("ldmatrix.sync.aligned.m8n8.x4.shared.b16 {%0,%1,%2,%3}, [%4];"
                 : "=r"(r[0]), "=r"(r[1]), "=r"(r[2]), "=r"(r[3]) : "r"(addr));
}

__device__ __forceinline__ void cpa16(uint32_t smem_dst, const float* gsrc) {
    asm volatile("cp.async.cg.shared.global [%0], [%1], 16;"
                 :: "r"(smem_dst), "l"(gsrc));
}
__device__ __forceinline__ uint32_t smem_u32(const void* p) {
    uint32_t a;
    asm("{ .reg .u64 t; cvta.to.shared.u64 t, %1; cvt.u32.u64 %0, t; }" : "=r"(a) : "l"(p));
    return a;
}

// ---------------- reductions --------------------------------------------------
__device__ __forceinline__ float warpRedMax(float v) {
#pragma unroll
    for (int o = 16; o > 0; o >>= 1) v = fmaxf(v, __shfl_xor_sync(0xffffffffu, v, o));
    return v;
}
__device__ __forceinline__ float warpRedSum(float v) {
#pragma unroll
    for (int o = 16; o > 0; o >>= 1) v += __shfl_xor_sync(0xffffffffu, v, o);
    return v;
}
__device__ __forceinline__ float blockRedMax(float v, float* red) {
    v = warpRedMax(v);
    if ((threadIdx.x & 31) == 0) red[threadIdx.x >> 5] = v;
    __syncthreads();
    if (threadIdx.x < 32) {
        float x = (threadIdx.x < (blockDim.x >> 5)) ? red[threadIdx.x] : -3.4e38f;
        x = warpRedMax(x);
        if (threadIdx.x == 0) red[0] = x;
    }
    __syncthreads();
    float r = red[0];
    __syncthreads();
    return r;
}
__device__ __forceinline__ float blockRedSum(float v, float* red) {
    v = warpRedSum(v);
    if ((threadIdx.x & 31) == 0) red[threadIdx.x >> 5] = v;
    __syncthreads();
    if (threadIdx.x < 32) {
        float x = (threadIdx.x < (blockDim.x >> 5)) ? red[threadIdx.x] : 0.f;
        x = warpRedSum(x);
        if (threadIdx.x == 0) red[0] = x;
    }
    __syncthreads();
    float r = red[0];
    __syncthreads();
    return r;
}

// ---------------- tf32 pre-round copy -----------------------------------------
__global__ void __launch_bounds__(256)
round_tf32_k(const float* __restrict__ in, float* __restrict__ out, int n4)
{
    int i = blockIdx.x * 256 + threadIdx.x;
    if (i < n4) {
        float4 v = reinterpret_cast<const float4*>(in)[i];
        v.x = rtf(v.x); v.y = rtf(v.y); v.z = rtf(v.z); v.w = rtf(v.w);
        reinterpret_cast<float4*>(out)[i] = v;
    }
}

// ============ TF32 GEMM: C = alpha * A @ B^T (+bias)(+silu)(+round) ===========
// Inputs MUST be pre-rounded to tf32. Block 128x128x32, 256 thr, 2-stage
// cp.async, ldmatrix fragment loads. mode bits: 1=bias, 2=silu, 4=round out.
__global__ void __launch_bounds__(256, 2)
gemm_nt_tf32(const float* __restrict__ A, const float* __restrict__ Bm,
             float* __restrict__ C, int Kd, int lda, int ldb, int ldc,
             long sA1, long sA2, long sB1, long sB2, long sC1, long sC2,
             float alpha, const float* __restrict__ bias, int mode)
{
    extern __shared__ uint32_t smbuf[];
    const uint32_t aBase = smem_u32(smbuf);                    // 2 x STAGE_WORDS (A)
    const uint32_t bBase = aBase + 2 * STAGE_WORDS * 4;        // 2 x STAGE_WORDS (B)

    const int z = blockIdx.z;
    const long zb = z >> 4, zh = z & 15;
    const float* Ab = A  + zb * sA1 + zh * sA2;
    const float* Bb = Bm + zb * sB1 + zh * sB2;
    float*       Cb = C  + zb * sC1 + zh * sC2;

    const int tid   = threadIdx.x;
    const int m0    = blockIdx.y * 128;
    const int n0    = blockIdx.x * 128;
    const int warp  = tid >> 5;
    const int lane  = tid & 31;
    const int warpM = warp & 1;
    const int warpN = warp >> 1;
    const int g     = lane >> 2;
    const int tg    = lane & 3;

    const int lr = tid >> 3;         // 0..31 (row)
    const int lc = (tid & 7) * 4;    // word offset 0..28

    // ldmatrix per-thread offsets (bytes within a stage)
    const uint32_t aFragOff =
        (uint32_t)(((warpM * 64 + (lane & 7) + ((lane >> 3) & 1) * 8) * SM_PITCH
                    + (lane >> 4) * 4) * 4);
    const uint32_t bFragOff =
        (uint32_t)(((warpN * 32 + (lane & 7) + (lane >> 4) * 8) * SM_PITCH
                    + ((lane >> 3) & 1) * 4) * 4);
    const uint32_t A_MT_STRIDE = 16 * SM_PITCH * 4;
    const uint32_t B_P_STRIDE  = 16 * SM_PITCH * 4;

    float acc[4][4][4];
#pragma unroll
    for (int mt = 0; mt < 4; mt++)
#pragma unroll
        for (int nt = 0; nt < 4; nt++)
#pragma unroll
            for (int r = 0; r < 4; r++) acc[mt][nt][r] = 0.f;

    // prefetch stage 0
#pragma unroll
    for (int i = 0; i < 4; i++) {
        const int r = lr + i * 32;
        cpa16(aBase + (uint32_t)((r * SM_PITCH + lc) * 4), &Ab[(long)(m0 + r) * lda + lc]);
        cpa16(bBase + (uint32_t)((r * SM_PITCH + lc) * 4), &Bb[(long)(n0 + r) * ldb + lc]);
    }
    asm volatile("cp.async.commit_group;");

    for (int k0 = 0; k0 < Kd; k0 += 32) {
        const int st = (k0 >> 5) & 1;
        if (k0 + 32 < Kd) {
            const int sn = st ^ 1;
            const uint32_t aOff = aBase + (uint32_t)(sn * STAGE_WORDS * 4);
            const uint32_t bOff = bBase + (uint32_t)(sn * STAGE_WORDS * 4);
#pragma unroll
            for (int i = 0; i < 4; i++) {
                const int r = lr + i * 32;
                cpa16(aOff + (uint32_t)((r * SM_PITCH + lc) * 4),
                      &Ab[(long)(m0 + r) * lda + k0 + 32 + lc]);
                cpa16(bOff + (uint32_t)((r * SM_PITCH + lc) * 4),
                      &Bb[(long)(n0 + r) * ldb + k0 + 32 + lc]);
            }
        }
        asm volatile("cp.async.commit_group;");
        asm volatile("cp.async.wait_group 1;");
        __syncthreads();

        const uint32_t aSt = aBase + (uint32_t)(st * STAGE_WORDS * 4) + aFragOff;
        const uint32_t bSt = bBase + (uint32_t)(st * STAGE_WORDS * 4) + bFragOff;
#pragma unroll
        for (int kk = 0; kk < 32; kk += 8) {
            uint32_t af[4][4], bf[4][2];
#pragma unroll
            for (int mt = 0; mt < 4; mt++)
                ldmx4(af[mt], aSt + mt * A_MT_STRIDE + kk * 4);
#pragma unroll
            for (int p = 0; p < 2; p++) {
                uint32_t t[4];
                ldmx4(t, bSt + p * B_P_STRIDE + kk * 4);
                bf[2 * p][0] = t[0]; bf[2 * p][1] = t[1];
                bf[2 * p + 1][0] = t[2]; bf[2 * p + 1][1] = t[3];
            }
#pragma unroll
            for (int mt = 0; mt < 4; mt++)
#pragma unroll
                for (int nt = 0; nt < 4; nt++)
                    mma_tf32(acc[mt][nt], af[mt][0], af[mt][1], af[mt][2], af[mt][3],
                             bf[nt][0], bf[nt][1]);
        }
        __syncthreads();
    }

#pragma unroll
    for (int mt = 0; mt < 4; mt++) {
#pragma unroll
        for (int nt = 0; nt < 4; nt++) {
            const long row = m0 + warpM * 64 + mt * 16 + g;
            const int  col = n0 + warpN * 32 + nt * 8 + 2 * tg;
            float v0 = acc[mt][nt][0] * alpha;
            float v1 = acc[mt][nt][1] * alpha;
            float v2 = acc[mt][nt][2] * alpha;
            float v3 = acc[mt][nt][3] * alpha;
            if (mode & 1) {
                const float bb0 = bias[col], bb1 = bias[col + 1];
                v0 += bb0; v1 += bb1; v2 += bb0; v3 += bb1;
            }
            if (mode & 2) {
                v0 = v0 / (1.f + expf(-v0));
                v1 = v1 / (1.f + expf(-v1));
                v2 = v2 / (1.f + expf(-v2));
                v3 = v3 / (1.f + expf(-v3));
            }
            if (mode & 4) { v0 = rtf(v0); v1 = rtf(v1); v2 = rtf(v2); v3 = rtf(v3); }
            *reinterpret_cast<float2*>(&Cb[row * ldc + col])       = make_float2(v0, v1);
            *reinterpret_cast<float2*>(&Cb[(row + 8) * ldc + col]) = make_float2(v2, v3);
        }
    }
}

// ============ TF32 attn2 @ V (NN, N=64, per (b,h)) ============================
__global__ void __launch_bounds__(256)
attn_v_tf32(const float* __restrict__ A2, const float* __restrict__ Vp,
            float* __restrict__ Cout)
{
    const int z  = blockIdx.z;
    const long zb = z >> 4, zh = z & 15;
    const float* Ab = A2 + (long)z * ((long)TQ_ * TK_);
    const float* Bb = Vp + zb * ((long)TK_ * D_) + zh * HD_;
    float*       Cb = Cout + zb * ((long)TQ_ * D_) + zh * HD_;
    const int m0 = blockIdx.y * 128;

    __shared__ uint32_t As[128][SM_PITCH];
    __shared__ uint32_t Bs[64][SM_PITCH];
    const uint32_t aB = smem_u32(&As[0][0]);
    const uint32_t bB = smem_u32(&Bs[0][0]);

    const int tid   = threadIdx.x;
    const int warp  = tid >> 5;
    const int lane  = tid & 31;
    const int warpM = warp & 3;
    const int warpN = warp >> 2;
    const int g     = lane >> 2;
    const int tg    = lane & 3;

    const int lr = tid >> 3;
    const int lc = (tid & 7) * 4;

    const uint32_t aFragOff =
        (uint32_t)(((warpM * 32 + (lane & 7) + ((lane >> 3) & 1) * 8) * SM_PITCH
                    + (lane >> 4) * 4) * 4);
    const uint32_t bFragOff =
        (uint32_t)(((warpN * 32 + (lane & 7) + (lane >> 4) * 8) * SM_PITCH
                    + ((lane >> 3) & 1) * 4) * 4);
    const uint32_t A_MT_STRIDE = 16 * SM_PITCH * 4;
    const uint32_t B_P_STRIDE  = 16 * SM_PITCH * 4;

    float acc[2][4][4];
#pragma unroll
    for (int mt = 0; mt < 2; mt++)
#pragma unroll
        for (int nt = 0; nt < 4; nt++)
#pragma unroll
            for (int r = 0; r < 4; r++) acc[mt][nt][r] = 0.f;

    for (int k0 = 0; k0 < TK_; k0 += 32) {
#pragma unroll
        for (int i = 0; i < 4; i++) {
            const int r = lr + i * 32;
            float4 av = *reinterpret_cast<const float4*>(&Ab[(long)(m0 + r) * TK_ + k0 + lc]);
            As[r][lc + 0] = __float_as_uint(av.x); As[r][lc + 1] = __float_as_uint(av.y);
            As[r][lc + 2] = __float_as_uint(av.z); As[r][lc + 3] = __float_as_uint(av.w);
        }
#pragma unroll
        for (int i = 0; i < 2; i++) {
            const int k = (tid >> 4) + i * 16;
            const int c = (tid & 15) * 4;
            float4 vv = *reinterpret_cast<const float4*>(&Bb[(long)(k0 + k) * D_ + c]);
            Bs[c + 0][k] = __float_as_uint(vv.x); Bs[c + 1][k] = __float_as_uint(vv.y);
            Bs[c + 2][k] = __float_as_uint(vv.z); Bs[c + 3][k] = __float_as_uint(vv.w);
        }
        __syncthreads();

#pragma unroll
        for (int kk = 0; kk < 32; kk += 8) {
            uint32_t af[2][4], bf[4][2];
#pragma unroll
            for (int mt = 0; mt < 2; mt++)
                ldmx4(af[mt], aB + aFragOff + mt * A_MT_STRIDE + kk * 4);
#pragma unroll
            for (int p = 0; p < 2; p++) {
                uint32_t t[4];
                ldmx4(t, bB + bFragOff + p * B_P_STRIDE + kk * 4);
                bf[2 * p][0] = t[0]; bf[2 * p][1] = t[1];
                bf[2 * p + 1][0] = t[2]; bf[2 * p + 1][1] = t[3];
            }
#pragma unroll
            for (int mt = 0; mt < 2; mt++)
#pragma unroll
                for (int nt = 0; nt < 4; nt++)
                    mma_tf32(acc[mt][nt], af[mt][0], af[mt][1], af[mt][2], af[mt][3],
                             bf[nt][0], bf[nt][1]);
        }
        __syncthreads();
    }

#pragma unroll
    for (int mt = 0; mt < 2; mt++) {
#pragma unroll
        for (int nt = 0; nt < 4; nt++) {
            const long row = m0 + warpM * 32 + mt * 16 + g;
            const int  col = warpN * 32 + nt * 8 + 2 * tg;
            *reinterpret_cast<float2*>(&Cb[row * D_ + col]) =
                make_float2(rtf(acc[mt][nt][0]), rtf(acc[mt][nt][1]));
            *reinterpret_cast<float2*>(&Cb[(row + 8) * D_ + col]) =
                make_float2(rtf(acc[mt][nt][2]), rtf(acc[mt][nt][3]));
        }
    }
}

// ---------------- softmax -> mask -> softmax2 ---------------------------------
__global__ void __launch_bounds__(256)
softmax_mask_k(float* __restrict__ scores, float* __restrict__ masked,
               const float* __restrict__ alphap)
{
    __shared__ float red[32];
    const long row = blockIdx.x;
    float4* srow = reinterpret_cast<float4*>(scores + row * 1024);
    float4* mrow = reinterpret_cast<float4*>(masked + row * 1024);
    const int tid = threadIdx.x;
    const float alpha = *alphap;

    float4 v4 = srow[tid];
    float v[4] = {v4.x, v4.y, v4.z, v4.w};

    float mx = fmaxf(fmaxf(v[0], v[1]), fmaxf(v[2], v[3]));
    mx = blockRedMax(mx, red);

    float e[4], s = 0.f;
#pragma unroll
    for (int i = 0; i < 4; i++) { e[i] = expf(v[i] - mx); s += e[i]; }
    s = blockRedSum(s, red);
    const float inv = 1.f / s;

    float mk[4];
#pragma unroll
    for (int i = 0; i < 4; i++) {
        float a = e[i] * inv;
        mk[i] = (a >= alpha) ? a : 0.f;
    }
    mrow[tid] = make_float4(mk[0], mk[1], mk[2], mk[3]);

    float mx2 = fmaxf(fmaxf(mk[0], mk[1]), fmaxf(mk[2], mk[3]));
    mx2 = blockRedMax(mx2, red);

    float e2[4], s2 = 0.f;
#pragma unroll
    for (int i = 0; i < 4; i++) { e2[i] = expf(mk[i] - mx2); s2 += e2[i]; }
    s2 = blockRedSum(s2, red);
    const float inv2 = 1.f / s2;

    srow[tid] = make_float4(rtf(e2[0] * inv2), rtf(e2[1] * inv2),
                            rtf(e2[2] * inv2), rtf(e2[3] * inv2));
}

// ---------------- out = LayerNorm(a + b) * g + beta ---------------------------
__global__ void __launch_bounds__(256)
add_ln_k(const float* __restrict__ A, const float* __restrict__ Bsrc,
         const float* __restrict__ g, const float* __restrict__ bet,
         float* __restrict__ out, float* __restrict__ out_r, int roundMain)
{
    __shared__ float red[32];
    const long row = blockIdx.x;
    const int tid = threadIdx.x;

    float4 a4 = reinterpret_cast<const float4*>(A    + row * 1024)[tid];
    float4 b4 = reinterpret_cast<const float4*>(Bsrc + row * 1024)[tid];
    float x[4] = {a4.x + b4.x, a4.y + b4.y, a4.z + b4.z, a4.w + b4.w};

    float s = x[0] + x[1] + x[2] + x[3];
    s = blockRedSum(s, red);
    const float mu = s * (1.f / 1024.f);

    float vs = 0.f;
#pragma unroll
    for (int i = 0; i < 4; i++) { float d = x[i] - mu; vs += d * d; }
    vs = blockRedSum(vs, red);
    const float inv = rsqrtf(vs * (1.f / 1024.f) + 1e-5f);

    float4 g4 = reinterpret_cast<const float4*>(g)[tid];
    float4 e4 = reinterpret_cast<const float4*>(bet)[tid];
    float o[4];
    o[0] = (x[0] - mu) * inv * g4.x + e4.x;
    o[1] = (x[1] - mu) * inv * g4.y + e4.y;
    o[2] = (x[2] - mu) * inv * g4.z + e4.z;
    o[3] = (x[3] - mu) * inv * g4.w + e4.w;

    float4 om;
    if (roundMain) om = make_float4(rtf(o[0]), rtf(o[1]), rtf(o[2]), rtf(o[3]));
    else           om = make_float4(o[0], o[1], o[2], o[3]);
    reinterpret_cast<float4*>(out + row * 1024)[tid] = om;
    if (out_r)
        reinterpret_cast<float4*>(out_r + row * 1024)[tid] =
            make_float4(rtf(o[0]), rtf(o[1]), rtf(o[2]), rtf(o[3]));
}

// ---------------- driver ------------------------------------------------------
extern "C" void kernel_launch(void* const* d_in, const int* in_sizes, int n_in,
                              void* d_out, int out_size)
{
    const float* base   = (const float*)d_in[0];
    const float* fusion = (const float*)d_in[1];
    const float* Wq     = (const float*)d_in[2];
    const float* Wk     = (const float*)d_in[3];
    const float* Wv     = (const float*)d_in[4];
    const float* Wo     = (const float*)d_in[5];
    const float* g1     = (const float*)d_in[6];
    const float* b1     = (const float*)d_in[7];
    const float* g2     = (const float*)d_in[8];
    const float* b2     = (const float*)d_in[9];
    const float* fc1_w  = (const float*)d_in[10];
    const float* fc1_b  = (const float*)d_in[11];
    const float* fc2_w  = (const float*)d_in[12];
    const float* fc2_b  = (const float*)d_in[13];
    const float* rw     = (const float*)d_in[14];
    const float* rbias  = (const float*)d_in[15];
    const float* alphap = (const float*)d_in[16];

    float* outf = (float*)d_out;
    float* outm = outf + (long)B_ * TQ_ * D_;

    float *q, *k, *v, *sc, *ao, *x, *w;
    cudaGetSymbolAddress((void**)&q,  g_q);
    cudaGetSymbolAddress((void**)&k,  g_k);
    cudaGetSymbolAddress((void**)&v,  g_v);
    cudaGetSymbolAddress((void**)&sc, g_sc);
    cudaGetSymbolAddress((void**)&ao, g_ao);
    cudaGetSymbolAddress((void**)&x,  g_x);
    cudaGetSymbolAddress((void**)&w,  g_w);

    cudaFuncSetAttribute(gemm_nt_tf32,
                         cudaFuncAttributeMaxDynamicSharedMemorySize, GEMM_SMEM_BYTES);

    const dim3 blk(256);
    const dim3 gBig(D_ / 128, (B_ * TQ_) / 128, 1);
    const int WN = 1024 * 1024;
    const int act4 = (B_ * TQ_ * D_) / 4;
    const int w4 = WN / 4;
    const int RB = 256;

    // pre-round external GEMM inputs to tf32 bits
    round_tf32_k<<<(act4 + RB - 1) / RB, RB>>>(base,   ao, act4);   // baseR -> g_ao
    round_tf32_k<<<(act4 + RB - 1) / RB, RB>>>(fusion, x,  act4);   // fusionR -> g_x
    const float* Ws[7] = {Wq, Wk, Wv, Wo, fc1_w, fc2_w, rw};
    for (int i = 0; i < 7; i++)
        round_tf32_k<<<(w4 + RB - 1) / RB, RB>>>(Ws[i], w + (long)i * WN, w4);
    const float *WqR = w, *WkR = w + WN, *WvR = w + 2L*WN, *WoR = w + 3L*WN,
                *f1R = w + 4L*WN, *f2R = w + 5L*WN, *rwR = w + 6L*WN;

    // Q/K/V projections (outputs rounded: feed GEMMs only)
    gemm_nt_tf32<<<gBig, blk, GEMM_SMEM_BYTES>>>(ao, WqR, q, D_, D_, D_, D_, 0,0,0,0,0,0, 1.f, nullptr, 4);
    gemm_nt_tf32<<<gBig, blk, GEMM_SMEM_BYTES>>>(x,  WkR, k, D_, D_, D_, D_, 0,0,0,0,0,0, 1.f, nullptr, 4);
    gemm_nt_tf32<<<gBig, blk, GEMM_SMEM_BYTES>>>(x,  WvR, v, D_, D_, D_, D_, 0,0,0,0,0,0, 1.f, nullptr, 4);

    // scores = Q K^T / 8 (exact output -> softmax)
    gemm_nt_tf32<<<dim3(TK_ / 128, TQ_ / 128, B_ * H_), blk, GEMM_SMEM_BYTES>>>(
        q, k, sc, HD_, D_, D_, TK_,
        (long)TQ_ * D_, HD_, (long)TK_ * D_, HD_,
        (long)H_ * TQ_ * TK_, (long)TQ_ * TK_,
        0.125f, nullptr, 0);

    // softmax -> masked (exact) -> attn2 (rounded, in place)
    softmax_mask_k<<<B_ * H_ * TQ_, blk>>>(sc, outm, alphap);

    // attn2 @ V -> ao (rounded)
    attn_v_tf32<<<dim3(1, TQ_ / 128, B_ * H_), blk>>>(sc, v, ao);

    // O projection (exact -> LN1)
    gemm_nt_tf32<<<gBig, blk, GEMM_SMEM_BYTES>>>(ao, WoR, q, D_, D_, D_, D_, 0,0,0,0,0,0, 1.f, nullptr, 0);

    // x = LN(base + proj): exact -> g_x, rounded copy -> g_ao
    add_ln_k<<<B_ * TQ_, blk>>>(base, q, g1, b1, x, ao, 0);

    // FFN: h1 = silu(xR fc1^T + b) rounded; ff = silu(h1 fc2^T + b) exact
    gemm_nt_tf32<<<gBig, blk, GEMM_SMEM_BYTES>>>(ao, f1R, k, D_, D_, D_, D_, 0,0,0,0,0,0, 1.f, fc1_b, 7);
    gemm_nt_tf32<<<gBig, blk, GEMM_SMEM_BYTES>>>(k,  f2R, v, D_, D_, D_, D_, 0,0,0,0,0,0, 1.f, fc2_b, 3);

    // y = LN(x + ff) rounded (feeds rw GEMM only)
    add_ln_k<<<B_ * TQ_, blk>>>(x, v, g2, b2, q, nullptr, 1);

    // final = y rw^T + rb (exact output)
    gemm_nt_tf32<<<gBig, blk, GEMM_SMEM_BYTES>>>(q, rwR, outf, D_, D_, D_, D_, 0,0,0,0,0,0, 1.f, rbias, 1);
}

// round 6
// speedup vs baseline: 1.7821x; 1.5516x over previous
#include <cuda_runtime.h>
#include <cuda_fp16.h>
#include <math.h>
#include <stdint.h>

#define B_  8
#define TQ_ 1024
#define TK_ 1024
#define D_  1024
#define H_  16
#define HD_ 64

#define KCH 64                     // k-chunk (halves)
#define HPITCH 144                 // bytes per smem row: 128 data + 16 pad
#define A_STAGE_B (128 * HPITCH)   // 18432 B (128-row tile)
#define B64_STAGE_B (64 * HPITCH)  // 9216 B  (64-row tile)
#define GEMMH_SMEM (2 * 2 * A_STAGE_B)                  // 73728 B
#define AV_SMEM    (2 * (A_STAGE_B + B64_STAGE_B))      // 55296 B

// ---------------- scratch (static device memory; no allocs allowed) -----------
__device__ __half g_baseh[B_*TQ_*D_];
__device__ __half g_fush [B_*TK_*D_];
__device__ __half g_qh[B_*TQ_*D_];
__device__ __half g_kh[B_*TK_*D_];
__device__ __half g_vh[B_*TK_*D_];
__device__ __half g_aoh[B_*TQ_*D_];
__device__ __half g_xh [B_*TQ_*D_];
__device__ __half g_h1h[B_*TQ_*D_];
__device__ __half g_yh [B_*TQ_*D_];
__device__ __half g_wh [7*1024*1024];
__device__ __half g_a2 [134217728];        // attn2 (fp16)
__device__ float  g_sc [134217728];        // scores (fp32)
__device__ float  g_x  [B_*TQ_*D_];        // x exact
__device__ float  g_wo [B_*TQ_*D_];        // Wo-out exact
__device__ float  g_ff [B_*TQ_*D_];        // ff exact

// ---------------- helpers ------------------------------------------------------
__device__ __forceinline__ void mma_f16(float* c,
                                        uint32_t a0, uint32_t a1, uint32_t a2, uint32_t a3,
                                        uint32_t b0, uint32_t b1) {
    asm volatile(
        "mma.sync.aligned.m16n8k16.row.col.f32.f16.f16.f32 "
        "{%0,%1,%2,%3}, {%4,%5,%6,%7}, {%8,%9}, {%0,%1,%2,%3};"
        : "+f"(c[0]), "+f"(c[1]), "+f"(c[2]), "+f"(c[3])
        : "r"(a0), "r"(a1), "r"(a2), "r"(a3), "r"(b0), "r"(b1));
}
__device__ __forceinline__ void ldmx4(uint32_t* r, uint32_t addr) {
    asm volatile("ldmatrix.sync.aligned.m8n8.x4.shared.b16 {%0,%1,%2,%3}, [%4];"
                 : "=r"(r[0]), "=r"(r[1]), "=r"(r[2]), "=r"(r[3]) : "r"(addr));
}
__device__ __forceinline__ void ldmx4t(uint32_t* r, uint32_t addr) {
    asm volatile("ldmatrix.sync.aligned.m8n8.x4.trans.shared.b16 {%0,%1,%2,%3}, [%4];"
                 : "=r"(r[0]), "=r"(r[1]), "=r"(r[2]), "=r"(r[3]) : "r"(addr));
}
__device__ __forceinline__ void cpa16(uint32_t smem_dst, const void* gsrc) {
    asm volatile("cp.async.cg.shared.global [%0], [%1], 16;"
                 :: "r"(smem_dst), "l"(gsrc));
}
__device__ __forceinline__ uint32_t smem_u32(const void* p) {
    uint32_t a;
    asm("{ .reg .u64 t; cvta.to.shared.u64 t, %1; cvt.u32.u64 %0, t; }" : "=r"(a) : "l"(p));
    return a;
}

// ---------------- reductions --------------------------------------------------
__device__ __forceinline__ float warpRedMax(float v) {
#pragma unroll
    for (int o = 16; o > 0; o >>= 1) v = fmaxf(v, __shfl_xor_sync(0xffffffffu, v, o));
    return v;
}
__device__ __forceinline__ float warpRedSum(float v) {
#pragma unroll
    for (int o = 16; o > 0; o >>= 1) v += __shfl_xor_sync(0xffffffffu, v, o);
    return v;
}
__device__ __forceinline__ float blockRedMax(float v, float* red) {
    v = warpRedMax(v);
    if ((threadIdx.x & 31) == 0) red[threadIdx.x >> 5] = v;
    __syncthreads();
    if (threadIdx.x < 32) {
        float x = (threadIdx.x < (blockDim.x >> 5)) ? red[threadIdx.x] : -3.4e38f;
        x = warpRedMax(x);
        if (threadIdx.x == 0) red[0] = x;
    }
    __syncthreads();
    float r = red[0];
    __syncthreads();
    return r;
}
__device__ __forceinline__ float blockRedSum(float v, float* red) {
    v = warpRedSum(v);
    if ((threadIdx.x & 31) == 0) red[threadIdx.x >> 5] = v;
    __syncthreads();
    if (threadIdx.x < 32) {
        float x = (threadIdx.x < (blockDim.x >> 5)) ? red[threadIdx.x] : 0.f;
        x = warpRedSum(x);
        if (threadIdx.x == 0) red[0] = x;
    }
    __syncthreads();
    float r = red[0];
    __syncthreads();
    return r;
}

// ---------------- f32 -> f16 convert -------------------------------------------
__global__ void __launch_bounds__(256)
conv_h_k(const float* __restrict__ in, __half* __restrict__ out, int n4)
{
    int i = blockIdx.x * 256 + threadIdx.x;
    if (i < n4) {
        float4 v = reinterpret_cast<const float4*>(in)[i];
        __half2* o = reinterpret_cast<__half2*>(out);
        o[2 * i]     = __floats2half2_rn(v.x, v.y);
        o[2 * i + 1] = __floats2half2_rn(v.z, v.w);
    }
}

// ============ FP16 GEMM: C = alpha * A @ B^T (+bias)(+silu) ===================
// A:[M,K] half lda, B:[N,K] half ldb, C:[M,N] (f32 or f16 per mode bit 8).
// Block 128x128x64, 256 thr, 2-stage cp.async, ldmatrix frags, m16n8k16 mma.
// mode bits: 1=bias, 2=silu, 8=half output. Batched z via strides (halves/elems).
__global__ void __launch_bounds__(256, 2)
gemm_h(const __half* __restrict__ A, const __half* __restrict__ Bm,
       void* __restrict__ Cv, int Kd, int lda, int ldb, int ldc,
       long sA1, long sA2, long sB1, long sB2, long sC1, long sC2,
       float alpha, const float* __restrict__ bias, int mode)
{
    extern __shared__ char smbuf[];
    const uint32_t aBase = smem_u32(smbuf);                 // 2 x A_STAGE_B
    const uint32_t bBase = aBase + 2 * A_STAGE_B;           // 2 x A_STAGE_B

    const int z = blockIdx.z;
    const long zb = z >> 4, zh = z & 15;
    const __half* Ab = A  + zb * sA1 + zh * sA2;
    const __half* Bb = Bm + zb * sB1 + zh * sB2;

    const int tid   = threadIdx.x;
    const int m0    = blockIdx.y * 128;
    const int n0    = blockIdx.x * 128;
    const int warp  = tid >> 5;
    const int lane  = tid & 31;
    const int warpM = warp & 1;
    const int warpN = warp >> 1;
    const int g     = lane >> 2;
    const int tg    = lane & 3;

    const int lr  = tid >> 3;        // staging row 0..31 (+32i)
    const int seg = (tid & 7) * 8;   // halves offset (16B chunks)

    const uint32_t aFragOff =
        (uint32_t)((warpM * 64 + (lane & 15)) * HPITCH + (lane >> 4) * 16);
    const uint32_t bFragOff =
        (uint32_t)(((warpN * 32 + (lane & 7) + ((lane >> 4) & 1) * 8)) * HPITCH
                   + ((lane >> 3) & 1) * 16);
    const uint32_t MT_STRIDE = 16 * HPITCH;

    float acc[4][4][4];
#pragma unroll
    for (int mt = 0; mt < 4; mt++)
#pragma unroll
        for (int nt = 0; nt < 4; nt++)
#pragma unroll
            for (int r = 0; r < 4; r++) acc[mt][nt][r] = 0.f;

    // prefetch stage 0
#pragma unroll
    for (int i = 0; i < 4; i++) {
        const int r = lr + i * 32;
        cpa16(aBase + (uint32_t)(r * HPITCH + seg * 2), &Ab[(long)(m0 + r) * lda + seg]);
        cpa16(bBase + (uint32_t)(r * HPITCH + seg * 2), &Bb[(long)(n0 + r) * ldb + seg]);
    }
    asm volatile("cp.async.commit_group;");

    for (int k0 = 0; k0 < Kd; k0 += KCH) {
        const int st = (k0 / KCH) & 1;
        if (k0 + KCH < Kd) {
            const int sn = st ^ 1;
            const uint32_t aOff = aBase + (uint32_t)(sn * A_STAGE_B);
            const uint32_t bOff = bBase + (uint32_t)(sn * A_STAGE_B);
#pragma unroll
            for (int i = 0; i < 4; i++) {
                const int r = lr + i * 32;
                cpa16(aOff + (uint32_t)(r * HPITCH + seg * 2),
                      &Ab[(long)(m0 + r) * lda + k0 + KCH + seg]);
                cpa16(bOff + (uint32_t)(r * HPITCH + seg * 2),
                      &Bb[(long)(n0 + r) * ldb + k0 + KCH + seg]);
            }
        }
        asm volatile("cp.async.commit_group;");
        asm volatile("cp.async.wait_group 1;");
        __syncthreads();

        const uint32_t aSt = aBase + (uint32_t)(st * A_STAGE_B) + aFragOff;
        const uint32_t bSt = bBase + (uint32_t)(st * A_STAGE_B) + bFragOff;
#pragma unroll
        for (int ks = 0; ks < 4; ks++) {          // 4 x k16 per chunk
            uint32_t af[4][4], bf[4][2];
#pragma unroll
            for (int mt = 0; mt < 4; mt++)
                ldmx4(af[mt], aSt + mt * MT_STRIDE + ks * 32);
#pragma unroll
            for (int p = 0; p < 2; p++) {
                uint32_t t[4];
                ldmx4(t, bSt + p * MT_STRIDE + ks * 32);
                bf[2 * p][0] = t[0]; bf[2 * p][1] = t[1];
                bf[2 * p + 1][0] = t[2]; bf[2 * p + 1][1] = t[3];
            }
#pragma unroll
            for (int mt = 0; mt < 4; mt++)
#pragma unroll
                for (int nt = 0; nt < 4; nt++)
                    mma_f16(acc[mt][nt], af[mt][0], af[mt][1], af[mt][2], af[mt][3],
                            bf[nt][0], bf[nt][1]);
        }
        __syncthreads();
    }

#pragma unroll
    for (int mt = 0; mt < 4; mt++) {
#pragma unroll
        for (int nt = 0; nt < 4; nt++) {
            const long row = m0 + warpM * 64 + mt * 16 + g;
            const int  col = n0 + warpN * 32 + nt * 8 + 2 * tg;
            float v0 = acc[mt][nt][0] * alpha;
            float v1 = acc[mt][nt][1] * alpha;
            float v2 = acc[mt][nt][2] * alpha;
            float v3 = acc[mt][nt][3] * alpha;
            if (mode & 1) {
                const float bb0 = bias[col], bb1 = bias[col + 1];
                v0 += bb0; v1 += bb1; v2 += bb0; v3 += bb1;
            }
            if (mode & 2) {
                v0 = v0 / (1.f + expf(-v0));
                v1 = v1 / (1.f + expf(-v1));
                v2 = v2 / (1.f + expf(-v2));
                v3 = v3 / (1.f + expf(-v3));
            }
            if (mode & 8) {
                __half* Ch = (__half*)Cv + zb * sC1 + zh * sC2;
                *reinterpret_cast<__half2*>(&Ch[row * ldc + col]) = __floats2half2_rn(v0, v1);
                *reinterpret_cast<__half2*>(&Ch[(row + 8) * ldc + col]) = __floats2half2_rn(v2, v3);
            } else {
                float* Cf = (float*)Cv + zb * sC1 + zh * sC2;
                *reinterpret_cast<float2*>(&Cf[row * ldc + col])       = make_float2(v0, v1);
                *reinterpret_cast<float2*>(&Cf[(row + 8) * ldc + col]) = make_float2(v2, v3);
            }
        }
    }
}

// ============ FP16 attn2 @ V (NN, N=64 per (b,h)) =============================
// A2 half [per z: TQ x TK]; V half [k][n] natural layout, trans-ldmatrix.
__global__ void __launch_bounds__(256)
attn_v_h(const __half* __restrict__ A2, const __half* __restrict__ Vp,
         __half* __restrict__ Cout)
{
    extern __shared__ char smbuf[];
    const uint32_t aBase = smem_u32(smbuf);                 // 2 x A_STAGE_B
    const uint32_t bBase = aBase + 2 * A_STAGE_B;           // 2 x B64_STAGE_B

    const int z  = blockIdx.z;
    const long zb = z >> 4, zh = z & 15;
    const __half* Ab = A2 + (long)z * ((long)TQ_ * TK_);
    const __half* Bb = Vp + zb * ((long)TK_ * D_) + zh * HD_;
    __half*       Cb = Cout + zb * ((long)TQ_ * D_) + zh * HD_;
    const int m0 = blockIdx.y * 128;

    const int tid   = threadIdx.x;
    const int warp  = tid >> 5;
    const int lane  = tid & 31;
    const int warpM = warp & 3;     // 4 x 32 rows
    const int warpN = warp >> 2;    // 2 x 32 cols
    const int g     = lane >> 2;
    const int tg    = lane & 3;

    const int lr  = tid >> 3;       // 0..31
    const int seg = (tid & 7) * 8;  // halves

    const uint32_t aFragOff =
        (uint32_t)((warpM * 32 + (lane & 15)) * HPITCH + (lane >> 4) * 16);
    // V: stored [k][n]; trans-ldmatrix. krow + n-byte offset.
    const uint32_t bFragOff =
        (uint32_t)(((lane & 7) + ((lane >> 3) & 1) * 8) * HPITCH + (lane >> 4) * 16);
    const uint32_t MT_STRIDE = 16 * HPITCH;

    float acc[2][4][4];
#pragma unroll
    for (int mt = 0; mt < 2; mt++)
#pragma unroll
        for (int nt = 0; nt < 4; nt++)
#pragma unroll
            for (int r = 0; r < 4; r++) acc[mt][nt][r] = 0.f;

    // prefetch stage 0
#pragma unroll
    for (int i = 0; i < 4; i++) {
        const int r = lr + i * 32;
        cpa16(aBase + (uint32_t)(r * HPITCH + seg * 2), &Ab[(long)(m0 + r) * TK_ + seg]);
    }
#pragma unroll
    for (int i = 0; i < 2; i++) {
        const int r = lr + i * 32;      // k-row 0..63
        cpa16(bBase + (uint32_t)(r * HPITCH + seg * 2), &Bb[(long)r * D_ + seg]);
    }
    asm volatile("cp.async.commit_group;");

    for (int k0 = 0; k0 < TK_; k0 += KCH) {
        const int st = (k0 / KCH) & 1;
        if (k0 + KCH < TK_) {
            const int sn = st ^ 1;
            const uint32_t aOff = aBase + (uint32_t)(sn * A_STAGE_B);
            const uint32_t bOff = bBase + (uint32_t)(sn * B64_STAGE_B);
#pragma unroll
            for (int i = 0; i < 4; i++) {
                const int r = lr + i * 32;
                cpa16(aOff + (uint32_t)(r * HPITCH + seg * 2),
                      &Ab[(long)(m0 + r) * TK_ + k0 + KCH + seg]);
            }
#pragma unroll
            for (int i = 0; i < 2; i++) {
                const int r = lr + i * 32;
                cpa16(bOff + (uint32_t)(r * HPITCH + seg * 2),
                      &Bb[(long)(k0 + KCH + r) * D_ + seg]);
            }
        }
        asm volatile("cp.async.commit_group;");
        asm volatile("cp.async.wait_group 1;");
        __syncthreads();

        const uint32_t aSt = aBase + (uint32_t)(st * A_STAGE_B) + aFragOff;
        const uint32_t bSt = bBase + (uint32_t)(st * B64_STAGE_B) + bFragOff;
#pragma unroll
        for (int ks = 0; ks < 4; ks++) {
            uint32_t af[2][4], bf[4][2];
#pragma unroll
            for (int mt = 0; mt < 2; mt++)
                ldmx4(af[mt], aSt + mt * MT_STRIDE + ks * 32);
#pragma unroll
            for (int p = 0; p < 2; p++) {
                uint32_t t[4];
                // k-step advances stored rows (k): +16 rows per ks; n offset: p*16 cols
                ldmx4t(t, bSt + ks * MT_STRIDE + (warpN * 32 + p * 16) * 2);
                bf[2 * p][0] = t[0]; bf[2 * p][1] = t[1];
                bf[2 * p + 1][0] = t[2]; bf[2 * p + 1][1] = t[3];
            }
#pragma unroll
            for (int mt = 0; mt < 2; mt++)
#pragma unroll
                for (int nt = 0; nt < 4; nt++)
                    mma_f16(acc[mt][nt], af[mt][0], af[mt][1], af[mt][2], af[mt][3],
                            bf[nt][0], bf[nt][1]);
        }
        __syncthreads();
    }

#pragma unroll
    for (int mt = 0; mt < 2; mt++) {
#pragma unroll
        for (int nt = 0; nt < 4; nt++) {
            const long row = m0 + warpM * 32 + mt * 16 + g;
            const int  col = warpN * 32 + nt * 8 + 2 * tg;
            *reinterpret_cast<__half2*>(&Cb[row * D_ + col]) =
                __floats2half2_rn(acc[mt][nt][0], acc[mt][nt][1]);
            *reinterpret_cast<__half2*>(&Cb[(row + 8) * D_ + col]) =
                __floats2half2_rn(acc[mt][nt][2], acc[mt][nt][3]);
        }
    }
}

// ---------------- softmax -> mask -> softmax2 ---------------------------------
// reads fp32 scores; writes masked fp32 + attn2 fp16.
__global__ void __launch_bounds__(256)
softmax_mask_k(const float* __restrict__ scores, float* __restrict__ masked,
               __half* __restrict__ a2, const float* __restrict__ alphap)
{
    __shared__ float red[32];
    const long row = blockIdx.x;
    const float4* srow = reinterpret_cast<const float4*>(scores + row * 1024);
    float4* mrow = reinterpret_cast<float4*>(masked + row * 1024);
    __half2* arow = reinterpret_cast<__half2*>(a2 + row * 1024);
    const int tid = threadIdx.x;
    const float alpha = *alphap;

    float4 v4 = srow[tid];
    float v[4] = {v4.x, v4.y, v4.z, v4.w};

    float mx = fmaxf(fmaxf(v[0], v[1]), fmaxf(v[2], v[3]));
    mx = blockRedMax(mx, red);

    float e[4], s = 0.f;
#pragma unroll
    for (int i = 0; i < 4; i++) { e[i] = expf(v[i] - mx); s += e[i]; }
    s = blockRedSum(s, red);
    const float inv = 1.f / s;

    float mk[4];
#pragma unroll
    for (int i = 0; i < 4; i++) {
        float a = e[i] * inv;
        mk[i] = (a >= alpha) ? a : 0.f;
    }
    mrow[tid] = make_float4(mk[0], mk[1], mk[2], mk[3]);

    float mx2 = fmaxf(fmaxf(mk[0], mk[1]), fmaxf(mk[2], mk[3]));
    mx2 = blockRedMax(mx2, red);

    float e2[4], s2 = 0.f;
#pragma unroll
    for (int i = 0; i < 4; i++) { e2[i] = expf(mk[i] - mx2); s2 += e2[i]; }
    s2 = blockRedSum(s2, red);
    const float inv2 = 1.f / s2;

    arow[2 * tid]     = __floats2half2_rn(e2[0] * inv2, e2[1] * inv2);
    arow[2 * tid + 1] = __floats2half2_rn(e2[2] * inv2, e2[3] * inv2);
}

// ---------------- LayerNorm(a + b) * g + beta ----------------------------------
// outF (fp32, optional), outH (fp16, optional)
__global__ void __launch_bounds__(256)
add_ln_k(const float* __restrict__ A, const float* __restrict__ Bsrc,
         const float* __restrict__ g, const float* __restrict__ bet,
         float* __restrict__ outF, __half* __restrict__ outH)
{
    __shared__ float red[32];
    const long row = blockIdx.x;
    const int tid = threadIdx.x;

    float4 a4 = reinterpret_cast<const float4*>(A    + row * 1024)[tid];
    float4 b4 = reinterpret_cast<const float4*>(Bsrc + row * 1024)[tid];
    float x[4] = {a4.x + b4.x, a4.y + b4.y, a4.z + b4.z, a4.w + b4.w};

    float s = x[0] + x[1] + x[2] + x[3];
    s = blockRedSum(s, red);
    const float mu = s * (1.f / 1024.f);

    float vs = 0.f;
#pragma unroll
    for (int i = 0; i < 4; i++) { float d = x[i] - mu; vs += d * d; }
    vs = blockRedSum(vs, red);
    const float inv = rsqrtf(vs * (1.f / 1024.f) + 1e-5f);

    float4 g4 = reinterpret_cast<const float4*>(g)[tid];
    float4 e4 = reinterpret_cast<const float4*>(bet)[tid];
    float o[4];
    o[0] = (x[0] - mu) * inv * g4.x + e4.x;
    o[1] = (x[1] - mu) * inv * g4.y + e4.y;
    o[2] = (x[2] - mu) * inv * g4.z + e4.z;
    o[3] = (x[3] - mu) * inv * g4.w + e4.w;

    if (outF)
        reinterpret_cast<float4*>(outF + row * 1024)[tid] =
            make_float4(o[0], o[1], o[2], o[3]);
    if (outH) {
        __half2* oh = reinterpret_cast<__half2*>(outH + row * 1024);
        oh[2 * tid]     = __floats2half2_rn(o[0], o[1]);
        oh[2 * tid + 1] = __floats2half2_rn(o[2], o[3]);
    }
}

// ---------------- driver ------------------------------------------------------
extern "C" void kernel_launch(void* const* d_in, const int* in_sizes, int n_in,
                              void* d_out, int out_size)
{
    const float* base   = (const float*)d_in[0];
    const float* fusion = (const float*)d_in[1];
    const float* Wq     = (const float*)d_in[2];
    const float* Wk     = (const float*)d_in[3];
    const float* Wv     = (const float*)d_in[4];
    const float* Wo     = (const float*)d_in[5];
    const float* g1     = (const float*)d_in[6];
    const float* b1     = (const float*)d_in[7];
    const float* g2     = (const float*)d_in[8];
    const float* b2     = (const float*)d_in[9];
    const float* fc1_w  = (const float*)d_in[10];
    const float* fc1_b  = (const float*)d_in[11];
    const float* fc2_w  = (const float*)d_in[12];
    const float* fc2_b  = (const float*)d_in[13];
    const float* rw     = (const float*)d_in[14];
    const float* rbias  = (const float*)d_in[15];
    const float* alphap = (const float*)d_in[16];

    float* outf = (float*)d_out;
    float* outm = outf + (long)B_ * TQ_ * D_;

    __half *baseh, *fush, *qh, *kh, *vh, *aoh, *xh, *h1h, *yh, *wh, *a2;
    float *sc, *x, *wo, *ff;
    cudaGetSymbolAddress((void**)&baseh, g_baseh);
    cudaGetSymbolAddress((void**)&fush,  g_fush);
    cudaGetSymbolAddress((void**)&qh,  g_qh);
    cudaGetSymbolAddress((void**)&kh,  g_kh);
    cudaGetSymbolAddress((void**)&vh,  g_vh);
    cudaGetSymbolAddress((void**)&aoh, g_aoh);
    cudaGetSymbolAddress((void**)&xh,  g_xh);
    cudaGetSymbolAddress((void**)&h1h, g_h1h);
    cudaGetSymbolAddress((void**)&yh,  g_yh);
    cudaGetSymbolAddress((void**)&wh,  g_wh);
    cudaGetSymbolAddress((void**)&a2,  g_a2);
    cudaGetSymbolAddress((void**)&sc,  g_sc);
    cudaGetSymbolAddress((void**)&x,   g_x);
    cudaGetSymbolAddress((void**)&wo,  g_wo);
    cudaGetSymbolAddress((void**)&ff,  g_ff);

    cudaFuncSetAttribute(gemm_h,
                         cudaFuncAttributeMaxDynamicSharedMemorySize, GEMMH_SMEM);
    cudaFuncSetAttribute(attn_v_h,
                         cudaFuncAttributeMaxDynamicSharedMemorySize, AV_SMEM);

    const dim3 blk(256);
    const dim3 gBig(D_ / 128, (B_ * TQ_) / 128, 1);
    const long WN = 1024 * 1024;
    const int act4 = (B_ * TQ_ * D_) / 4;
    const int w4 = (int)(WN / 4);
    const int RB = 256;

    // convert external inputs to fp16
    conv_h_k<<<(act4 + RB - 1) / RB, RB>>>(base,   baseh, act4);
    conv_h_k<<<(act4 + RB - 1) / RB, RB>>>(fusion, fush,  act4);
    const float* Ws[7] = {Wq, Wk, Wv, Wo, fc1_w, fc2_w, rw};
    for (int i = 0; i < 7; i++)
        conv_h_k<<<(w4 + RB - 1) / RB, RB>>>(Ws[i], wh + (long)i * WN, w4);
    const __half *WqH = wh, *WkH = wh + WN, *WvH = wh + 2*WN, *WoH = wh + 3*WN,
                 *f1H = wh + 4*WN, *f2H = wh + 5*WN, *rwH = wh + 6*WN;

    // Q/K/V projections (fp16 out)
    gemm_h<<<gBig, blk, GEMMH_SMEM>>>(baseh, WqH, qh, D_, D_, D_, D_,
                                      0,0,0,0,0,0, 1.f, nullptr, 8);
    gemm_h<<<gBig, blk, GEMMH_SMEM>>>(fush,  WkH, kh, D_, D_, D_, D_,
                                      0,0,0,0,0,0, 1.f, nullptr, 8);
    gemm_h<<<gBig, blk, GEMMH_SMEM>>>(fush,  WvH, vh, D_, D_, D_, D_,
                                      0,0,0,0,0,0, 1.f, nullptr, 8);

    // scores = Q K^T / 8 (fp32 out)
    gemm_h<<<dim3(TK_ / 128, TQ_ / 128, B_ * H_), blk, GEMMH_SMEM>>>(
        qh, kh, sc, HD_, D_, D_, TK_,
        (long)TQ_ * D_, HD_, (long)TK_ * D_, HD_,
        (long)H_ * TQ_ * TK_, (long)TQ_ * TK_,
        0.125f, nullptr, 0);

    // softmax -> masked (fp32) -> attn2 (fp16)
    softmax_mask_k<<<B_ * H_ * TQ_, blk>>>(sc, outm, a2, alphap);

    // attn2 @ V -> ao (fp16)
    attn_v_h<<<dim3(1, TQ_ / 128, B_ * H_), blk, AV_SMEM>>>(a2, vh, aoh);

    // O projection (fp32 out -> LN1)
    gemm_h<<<gBig, blk, GEMMH_SMEM>>>(aoh, WoH, wo, D_, D_, D_, D_,
                                      0,0,0,0,0,0, 1.f, nullptr, 0);

    // x = LN(base + wo): fp32 -> x, fp16 -> xh
    add_ln_k<<<B_ * TQ_, blk>>>(base, wo, g1, b1, x, xh);

    // FFN
    gemm_h<<<gBig, blk, GEMMH_SMEM>>>(xh,  f1H, h1h, D_, D_, D_, D_,
                                      0,0,0,0,0,0, 1.f, fc1_b, 11);   // bias+silu+half
    gemm_h<<<gBig, blk, GEMMH_SMEM>>>(h1h, f2H, ff,  D_, D_, D_, D_,
                                      0,0,0,0,0,0, 1.f, fc2_b, 3);    // bias+silu fp32

    // y = LN(x + ff): fp16 -> yh
    add_ln_k<<<B_ * TQ_, blk>>>(x, ff, g2, b2, nullptr, yh);

    // final = y rw^T + rb (fp32 out)
    gemm_h<<<gBig, blk, GEMMH_SMEM>>>(yh, rwH, outf, D_, D_, D_, D_,
                                      0,0,0,0,0,0, 1.f, rbias, 1);
}

// round 8
// speedup vs baseline: 1.8139x; 1.0178x over previous
#include <cuda_runtime.h>
#include <cuda_fp16.h>
#include <math.h>
#include <stdint.h>
#include <string.h>

#define B_  8
#define TQ_ 1024
#define TK_ 1024
#define D_  1024
#define H_  16
#define HD_ 64

#define KCH 64
#define HPITCH 144
#define A_STAGE_B (128 * HPITCH)
#define GEMMH_SMEM (2 * 2 * A_STAGE_B)

// fused attention smem layout
#define FA_PITCH 144
#define FA_KVBUF (1024 * FA_PITCH)           // 147456 (K, later V)
#define FA_QOFF  FA_KVBUF                    // Q: 16 rows x 144B = 2304
#define FA_ORED  (FA_KVBUF + 2560)           // 150016, warp-partial O
#define FA_OROW  68                          // padded row stride (words)
#define FA_OWARP (16 * FA_OROW)              // 1088 words per warp
#define FA_SMEM  (FA_ORED + 8 * FA_OWARP * 4)  // 150016+34816=184832

// ---------------- scratch -------------------------------------------------------
__device__ __half g_baseh[B_*TQ_*D_];
__device__ __half g_fush [B_*TK_*D_];
__device__ __half g_qh[B_*TQ_*D_];
__device__ __half g_kh[B_*TK_*D_];
__device__ __half g_vh[B_*TK_*D_];
__device__ __half g_aoh[B_*TQ_*D_];
__device__ __half g_xh [B_*TQ_*D_];
__device__ __half g_h1h[B_*TQ_*D_];
__device__ __half g_yh [B_*TQ_*D_];
__device__ __half g_wh [7*1024*1024];
__device__ float  g_x  [B_*TQ_*D_];
__device__ float  g_wo [B_*TQ_*D_];
__device__ float  g_ff [B_*TQ_*D_];

// ---------------- helpers -------------------------------------------------------
__device__ __forceinline__ void mma_f16(float* c,
                                        uint32_t a0, uint32_t a1, uint32_t a2, uint32_t a3,
                                        uint32_t b0, uint32_t b1) {
    asm volatile(
        "mma.sync.aligned.m16n8k16.row.col.f32.f16.f16.f32 "
        "{%0,%1,%2,%3}, {%4,%5,%6,%7}, {%8,%9}, {%0,%1,%2,%3};"
        : "+f"(c[0]), "+f"(c[1]), "+f"(c[2]), "+f"(c[3])
        : "r"(a0), "r"(a1), "r"(a2), "r"(a3), "r"(b0), "r"(b1));
}
__device__ __forceinline__ void ldmx4(uint32_t* r, uint32_t addr) {
    asm volatile("ldmatrix.sync.aligned.m8n8.x4.shared.b16 {%0,%1,%2,%3}, [%4];"
                 : "=r"(r[0]), "=r"(r[1]), "=r"(r[2]), "=r"(r[3]) : "r"(addr));
}
__device__ __forceinline__ void ldmx4t(uint32_t* r, uint32_t addr) {
    asm volatile("ldmatrix.sync.aligned.m8n8.x4.trans.shared.b16 {%0,%1,%2,%3}, [%4];"
                 : "=r"(r[0]), "=r"(r[1]), "=r"(r[2]), "=r"(r[3]) : "r"(addr));
}
__device__ __forceinline__ void cpa16(uint32_t smem_dst, const void* gsrc) {
    asm volatile("cp.async.cg.shared.global [%0], [%1], 16;"
                 :: "r"(smem_dst), "l"(gsrc));
}
__device__ __forceinline__ uint32_t smem_u32(const void* p) {
    uint32_t a;
    asm("{ .reg .u64 t; cvta.to.shared.u64 t, %1; cvt.u32.u64 %0, t; }" : "=r"(a) : "l"(p));
    return a;
}
__device__ __forceinline__ uint32_t packh2(float a, float b) {
    uint32_t r;
    asm("cvt.rn.f16x2.f32 %0, %2, %1;" : "=r"(r) : "f"(a), "f"(b));
    return r;   // lo = a, hi = b (first src operand -> high half)
}

// ---------------- reductions (block) --------------------------------------------
__device__ __forceinline__ float warpRedSum(float v) {
#pragma unroll
    for (int o = 16; o > 0; o >>= 1) v += __shfl_xor_sync(0xffffffffu, v, o);
    return v;
}
__device__ __forceinline__ float blockRedSum(float v, float* red) {
    v = warpRedSum(v);
    if ((threadIdx.x & 31) == 0) red[threadIdx.x >> 5] = v;
    __syncthreads();
    if (threadIdx.x < 32) {
        float x = (threadIdx.x < (blockDim.x >> 5)) ? red[threadIdx.x] : 0.f;
        x = warpRedSum(x);
        if (threadIdx.x == 0) red[0] = x;
    }
    __syncthreads();
    float r = red[0];
    __syncthreads();
    return r;
}

// ---------------- f32 -> f16 convert --------------------------------------------
__global__ void __launch_bounds__(256)
conv_h_k(const float* __restrict__ in, __half* __restrict__ out, int n4)
{
    int i = blockIdx.x * 256 + threadIdx.x;
    if (i < n4) {
        float4 v = reinterpret_cast<const float4*>(in)[i];
        __half2* o = reinterpret_cast<__half2*>(out);
        o[2 * i]     = __floats2half2_rn(v.x, v.y);
        o[2 * i + 1] = __floats2half2_rn(v.z, v.w);
    }
}

// ============ FP16 GEMM (R6-validated) =========================================
__global__ void __launch_bounds__(256, 2)
gemm_h(const __half* __restrict__ A, const __half* __restrict__ Bm,
       void* __restrict__ Cv, int Kd, int lda, int ldb, int ldc,
       float alpha, const float* __restrict__ bias, int mode)
{
    extern __shared__ char smbuf[];
    const uint32_t aBase = smem_u32(smbuf);
    const uint32_t bBase = aBase + 2 * A_STAGE_B;

    const __half* Ab = A;
    const __half* Bb = Bm;

    const int tid   = threadIdx.x;
    const int m0    = blockIdx.y * 128;
    const int n0    = blockIdx.x * 128;
    const int warp  = tid >> 5;
    const int lane  = tid & 31;
    const int warpM = warp & 1;
    const int warpN = warp >> 1;
    const int g     = lane >> 2;
    const int tg    = lane & 3;

    const int lr  = tid >> 3;
    const int seg = (tid & 7) * 8;

    const uint32_t aFragOff =
        (uint32_t)((warpM * 64 + (lane & 15)) * HPITCH + (lane >> 4) * 16);
    const uint32_t bFragOff =
        (uint32_t)(((warpN * 32 + (lane & 7) + ((lane >> 4) & 1) * 8)) * HPITCH
                   + ((lane >> 3) & 1) * 16);
    const uint32_t MT_STRIDE = 16 * HPITCH;

    float acc[4][4][4];
#pragma unroll
    for (int mt = 0; mt < 4; mt++)
#pragma unroll
        for (int nt = 0; nt < 4; nt++)
#pragma unroll
            for (int r = 0; r < 4; r++) acc[mt][nt][r] = 0.f;

#pragma unroll
    for (int i = 0; i < 4; i++) {
        const int r = lr + i * 32;
        cpa16(aBase + (uint32_t)(r * HPITCH + seg * 2), &Ab[(long)(m0 + r) * lda + seg]);
        cpa16(bBase + (uint32_t)(r * HPITCH + seg * 2), &Bb[(long)(n0 + r) * ldb + seg]);
    }
    asm volatile("cp.async.commit_group;");

    for (int k0 = 0; k0 < Kd; k0 += KCH) {
        const int st = (k0 / KCH) & 1;
        if (k0 + KCH < Kd) {
            const int sn = st ^ 1;
            const uint32_t aOff = aBase + (uint32_t)(sn * A_STAGE_B);
            const uint32_t bOff = bBase + (uint32_t)(sn * A_STAGE_B);
#pragma unroll
            for (int i = 0; i < 4; i++) {
                const int r = lr + i * 32;
                cpa16(aOff + (uint32_t)(r * HPITCH + seg * 2),
                      &Ab[(long)(m0 + r) * lda + k0 + KCH + seg]);
                cpa16(bOff + (uint32_t)(r * HPITCH + seg * 2),
                      &Bb[(long)(n0 + r) * ldb + k0 + KCH + seg]);
            }
        }
        asm volatile("cp.async.commit_group;");
        asm volatile("cp.async.wait_group 1;");
        __syncthreads();

        const uint32_t aSt = aBase + (uint32_t)(st * A_STAGE_B) + aFragOff;
        const uint32_t bSt = bBase + (uint32_t)(st * A_STAGE_B) + bFragOff;
#pragma unroll
        for (int ks = 0; ks < 4; ks++) {
            uint32_t af[4][4], bf[4][2];
#pragma unroll
            for (int mt = 0; mt < 4; mt++)
                ldmx4(af[mt], aSt + mt * MT_STRIDE + ks * 32);
#pragma unroll
            for (int p = 0; p < 2; p++) {
                uint32_t t[4];
                ldmx4(t, bSt + p * MT_STRIDE + ks * 32);
                bf[2 * p][0] = t[0]; bf[2 * p][1] = t[1];
                bf[2 * p + 1][0] = t[2]; bf[2 * p + 1][1] = t[3];
            }
#pragma unroll
            for (int mt = 0; mt < 4; mt++)
#pragma unroll
                for (int nt = 0; nt < 4; nt++)
                    mma_f16(acc[mt][nt], af[mt][0], af[mt][1], af[mt][2], af[mt][3],
                            bf[nt][0], bf[nt][1]);
        }
        __syncthreads();
    }

#pragma unroll
    for (int mt = 0; mt < 4; mt++) {
#pragma unroll
        for (int nt = 0; nt < 4; nt++) {
            const long row = m0 + warpM * 64 + mt * 16 + g;
            const int  col = n0 + warpN * 32 + nt * 8 + 2 * tg;
            float v0 = acc[mt][nt][0] * alpha;
            float v1 = acc[mt][nt][1] * alpha;
            float v2 = acc[mt][nt][2] * alpha;
            float v3 = acc[mt][nt][3] * alpha;
            if (mode & 1) {
                const float bb0 = bias[col], bb1 = bias[col + 1];
                v0 += bb0; v1 += bb1; v2 += bb0; v3 += bb1;
            }
            if (mode & 2) {
                v0 = v0 / (1.f + expf(-v0));
                v1 = v1 / (1.f + expf(-v1));
                v2 = v2 / (1.f + expf(-v2));
                v3 = v3 / (1.f + expf(-v3));
            }
            if (mode & 8) {
                __half* Ch = (__half*)Cv;
                *reinterpret_cast<__half2*>(&Ch[row * ldc + col]) = __floats2half2_rn(v0, v1);
                *reinterpret_cast<__half2*>(&Ch[(row + 8) * ldc + col]) = __floats2half2_rn(v2, v3);
            } else {
                float* Cf = (float*)Cv;
                *reinterpret_cast<float2*>(&Cf[row * ldc + col])       = make_float2(v0, v1);
                *reinterpret_cast<float2*>(&Cf[(row + 8) * ldc + col]) = make_float2(v2, v3);
            }
        }
    }
}

// ============ Fused attention: QK^T + softmax + mask + softmax2 + P@V =========
// Grid: (TQ/16, B*H). 256 thr. Warp w owns keys [w*128, w*128+128).
__global__ void __launch_bounds__(256, 1)
fattn_k(const __half* __restrict__ Qg, const __half* __restrict__ Kg,
        const __half* __restrict__ Vg, float* __restrict__ maskedG,
        __half* __restrict__ Og, const float* __restrict__ alphap)
{
    extern __shared__ char smc[];
    const uint32_t kvB = smem_u32(smc);
    const uint32_t qB  = kvB + FA_QOFF;
    float* Ored = reinterpret_cast<float*>(smc + FA_ORED);
    __shared__ float redm[128];
    __shared__ float redf[16];

    const int tid  = threadIdx.x;
    const int w    = tid >> 5, lane = tid & 31;
    const int g    = lane >> 2, tg = lane & 3;
    const int m0   = blockIdx.x * 16;
    const int z    = blockIdx.y;
    const long zb  = z >> 4, zh = z & 15;

    const __half* Qb = Qg + zb * (long)(TQ_ * D_) + zh * HD_;
    const __half* Kb = Kg + zb * (long)(TK_ * D_) + zh * HD_;
    const __half* Vb = Vg + zb * (long)(TK_ * D_) + zh * HD_;

    // ---- load Q (16x64) + K (1024x64) ----
    if (tid < 128) {
        const int r = tid >> 3, s = tid & 7;
        cpa16(qB + (uint32_t)(r * FA_PITCH + s * 16), Qb + (long)(m0 + r) * D_ + s * 8);
    }
#pragma unroll
    for (int i = 0; i < 32; i++) {
        const int idx = i * 256 + tid;
        const int r = idx >> 3, s = idx & 7;
        cpa16(kvB + (uint32_t)(r * FA_PITCH + s * 16), Kb + (long)r * D_ + s * 8);
    }
    asm volatile("cp.async.commit_group;");
    asm volatile("cp.async.wait_group 0;");
    __syncthreads();

    // ---- QK^T ----
    float acc[16][4];
#pragma unroll
    for (int nt = 0; nt < 16; nt++)
#pragma unroll
        for (int r = 0; r < 4; r++) acc[nt][r] = 0.f;

    const uint32_t aOff = qB + (uint32_t)((lane & 15) * FA_PITCH + (lane >> 4) * 16);
    const uint32_t bOff = kvB + (uint32_t)((w * 128 + (lane & 7) + ((lane >> 4) & 1) * 8) * FA_PITCH
                                           + ((lane >> 3) & 1) * 16);
#pragma unroll
    for (int ks = 0; ks < 4; ks++) {
        uint32_t a[4];
        ldmx4(a, aOff + ks * 32);
#pragma unroll
        for (int nt2 = 0; nt2 < 8; nt2++) {
            uint32_t t[4];
            ldmx4(t, bOff + (uint32_t)(nt2 * 16 * FA_PITCH) + ks * 32);
            mma_f16(acc[2 * nt2],     a[0], a[1], a[2], a[3], t[0], t[1]);
            mma_f16(acc[2 * nt2 + 1], a[0], a[1], a[2], a[3], t[2], t[3]);
        }
    }
    __syncthreads();                 // all warps done reading K

    // ---- start V load into the same buffer (overlapped with softmax) ----
#pragma unroll
    for (int i = 0; i < 32; i++) {
        const int idx = i * 256 + tid;
        const int r = idx >> 3, s = idx & 7;
        cpa16(kvB + (uint32_t)(r * FA_PITCH + s * 16), Vb + (long)r * D_ + s * 8);
    }
    asm volatile("cp.async.commit_group;");

    // ---- scale ----
#pragma unroll
    for (int nt = 0; nt < 16; nt++)
#pragma unroll
        for (int r = 0; r < 4; r++) acc[nt][r] *= 0.125f;

    // ---- softmax1: row max ----
    float lo = -1e30f, hi = -1e30f;
#pragma unroll
    for (int nt = 0; nt < 16; nt++) {
        lo = fmaxf(lo, fmaxf(acc[nt][0], acc[nt][1]));
        hi = fmaxf(hi, fmaxf(acc[nt][2], acc[nt][3]));
    }
    lo = fmaxf(lo, __shfl_xor_sync(~0u, lo, 1)); lo = fmaxf(lo, __shfl_xor_sync(~0u, lo, 2));
    hi = fmaxf(hi, __shfl_xor_sync(~0u, hi, 1)); hi = fmaxf(hi, __shfl_xor_sync(~0u, hi, 2));
    if (tg == 0) { redm[w * 16 + g] = lo; redm[w * 16 + 8 + g] = hi; }
    __syncthreads();
    if (tid < 16) {
        float m = -1e30f;
#pragma unroll
        for (int ww = 0; ww < 8; ww++) m = fmaxf(m, redm[ww * 16 + tid]);
        redf[tid] = m;
    }
    __syncthreads();
    lo = redf[g]; hi = redf[g + 8];
    __syncthreads();

    // ---- exp + row sum ----
    float slo = 0.f, shi = 0.f;
#pragma unroll
    for (int nt = 0; nt < 16; nt++) {
        acc[nt][0] = expf(acc[nt][0] - lo);
        acc[nt][1] = expf(acc[nt][1] - lo);
        acc[nt][2] = expf(acc[nt][2] - hi);
        acc[nt][3] = expf(acc[nt][3] - hi);
        slo += acc[nt][0] + acc[nt][1];
        shi += acc[nt][2] + acc[nt][3];
    }
    slo += __shfl_xor_sync(~0u, slo, 1); slo += __shfl_xor_sync(~0u, slo, 2);
    shi += __shfl_xor_sync(~0u, shi, 1); shi += __shfl_xor_sync(~0u, shi, 2);
    if (tg == 0) { redm[w * 16 + g] = slo; redm[w * 16 + 8 + g] = shi; }
    __syncthreads();
    if (tid < 16) {
        float s = 0.f;
#pragma unroll
        for (int ww = 0; ww < 8; ww++) s += redm[ww * 16 + tid];
        redf[tid] = s;
    }
    __syncthreads();
    const float ilo = 1.f / redf[g], ihi = 1.f / redf[g + 8];
    __syncthreads();

    // ---- attn, mask, write masked ----
    const float alpha = *alphap;
    {
        float* m0p = maskedG + (long)z * TQ_ * TK_ + (long)(m0 + g) * 1024 + w * 128 + 2 * tg;
        float* m1p = m0p + 8L * 1024;
#pragma unroll
        for (int nt = 0; nt < 16; nt++) {
            float a0 = acc[nt][0] * ilo; if (a0 < alpha) a0 = 0.f;
            float a1 = acc[nt][1] * ilo; if (a1 < alpha) a1 = 0.f;
            float a2 = acc[nt][2] * ihi; if (a2 < alpha) a2 = 0.f;
            float a3 = acc[nt][3] * ihi; if (a3 < alpha) a3 = 0.f;
            *reinterpret_cast<float2*>(m0p + nt * 8) = make_float2(a0, a1);
            *reinterpret_cast<float2*>(m1p + nt * 8) = make_float2(a2, a3);
            acc[nt][0] = a0; acc[nt][1] = a1; acc[nt][2] = a2; acc[nt][3] = a3;
        }
    }

    // ---- softmax2: max ----
    lo = -1e30f; hi = -1e30f;
#pragma unroll
    for (int nt = 0; nt < 16; nt++) {
        lo = fmaxf(lo, fmaxf(acc[nt][0], acc[nt][1]));
        hi = fmaxf(hi, fmaxf(acc[nt][2], acc[nt][3]));
    }
    lo = fmaxf(lo, __shfl_xor_sync(~0u, lo, 1)); lo = fmaxf(lo, __shfl_xor_sync(~0u, lo, 2));
    hi = fmaxf(hi, __shfl_xor_sync(~0u, hi, 1)); hi = fmaxf(hi, __shfl_xor_sync(~0u, hi, 2));
    if (tg == 0) { redm[w * 16 + g] = lo; redm[w * 16 + 8 + g] = hi; }
    __syncthreads();
    if (tid < 16) {
        float m = -1e30f;
#pragma unroll
        for (int ww = 0; ww < 8; ww++) m = fmaxf(m, redm[ww * 16 + tid]);
        redf[tid] = m;
    }
    __syncthreads();
    lo = redf[g]; hi = redf[g + 8];
    __syncthreads();

    // ---- softmax2: exp + sum ----
    slo = 0.f; shi = 0.f;
#pragma unroll
    for (int nt = 0; nt < 16; nt++) {
        acc[nt][0] = expf(acc[nt][0] - lo);
        acc[nt][1] = expf(acc[nt][1] - lo);
        acc[nt][2] = expf(acc[nt][2] - hi);
        acc[nt][3] = expf(acc[nt][3] - hi);
        slo += acc[nt][0] + acc[nt][1];
        shi += acc[nt][2] + acc[nt][3];
    }
    slo += __shfl_xor_sync(~0u, slo, 1); slo += __shfl_xor_sync(~0u, slo, 2);
    shi += __shfl_xor_sync(~0u, shi, 1); shi += __shfl_xor_sync(~0u, shi, 2);
    if (tg == 0) { redm[w * 16 + g] = slo; redm[w * 16 + 8 + g] = shi; }
    __syncthreads();
    if (tid < 16) {
        float s = 0.f;
#pragma unroll
        for (int ww = 0; ww < 8; ww++) s += redm[ww * 16 + tid];
        redf[tid] = s;
    }
    __syncthreads();
    const float i2lo = 1.f / redf[g], i2hi = 1.f / redf[g + 8];

    // ---- wait for V, then P@V (P packed from registers) ----
    asm volatile("cp.async.wait_group 0;");
    __syncthreads();

    float o[8][4];
#pragma unroll
    for (int nt = 0; nt < 8; nt++)
#pragma unroll
        for (int r = 0; r < 4; r++) o[nt][r] = 0.f;

    const uint32_t vOff = kvB + (uint32_t)(((lane & 7) + ((lane >> 3) & 1) * 8) * FA_PITCH
                                           + (lane >> 4) * 16);
#pragma unroll
    for (int s = 0; s < 8; s++) {
        uint32_t af0 = packh2(acc[2 * s][0] * i2lo,     acc[2 * s][1] * i2lo);
        uint32_t af1 = packh2(acc[2 * s][2] * i2hi,     acc[2 * s][3] * i2hi);
        uint32_t af2 = packh2(acc[2 * s + 1][0] * i2lo, acc[2 * s + 1][1] * i2lo);
        uint32_t af3 = packh2(acc[2 * s + 1][2] * i2hi, acc[2 * s + 1][3] * i2hi);
        const uint32_t vRow = vOff + (uint32_t)((w * 128 + s * 16) * FA_PITCH);
#pragma unroll
        for (int p = 0; p < 4; p++) {
            uint32_t t[4];
            ldmx4t(t, vRow + p * 32);
            mma_f16(o[2 * p],     af0, af1, af2, af3, t[0], t[1]);
            mma_f16(o[2 * p + 1], af0, af1, af2, af3, t[2], t[3]);
        }
    }

    // ---- cross-warp O reduce via smem ----
#pragma unroll
    for (int nt = 0; nt < 8; nt++) {
        const int c = nt * 8 + 2 * tg;
        Ored[w * FA_OWARP + g * FA_OROW + c]           = o[nt][0];
        Ored[w * FA_OWARP + g * FA_OROW + c + 1]       = o[nt][1];
        Ored[w * FA_OWARP + (g + 8) * FA_OROW + c]     = o[nt][2];
        Ored[w * FA_OWARP + (g + 8) * FA_OROW + c + 1] = o[nt][3];
    }
    __syncthreads();
    {
        const int e = tid * 4;
        const int r = e >> 6, c = e & 63;
        float s0 = 0.f, s1 = 0.f, s2 = 0.f, s3 = 0.f;
#pragma unroll
        for (int ww = 0; ww < 8; ww++) {
            const float* p = &Ored[ww * FA_OWARP + r * FA_OROW + c];
            s0 += p[0]; s1 += p[1]; s2 += p[2]; s3 += p[3];
        }
        __half2 h0 = __floats2half2_rn(s0, s1);
        __half2 h1 = __floats2half2_rn(s2, s3);
        __half2* op = reinterpret_cast<__half2*>(
            Og + zb * (long)(TQ_ * D_) + (long)(m0 + r) * D_ + zh * HD_ + c);
        op[0] = h0; op[1] = h1;
    }
}

// ---------------- LayerNorm(a + b) * g + beta ------------------------------------
__global__ void __launch_bounds__(256)
add_ln_k(const float* __restrict__ A, const float* __restrict__ Bsrc,
         const float* __restrict__ g, const float* __restrict__ bet,
         float* __restrict__ outF, __half* __restrict__ outH)
{
    __shared__ float red[32];
    const long row = blockIdx.x;
    const int tid = threadIdx.x;

    float4 a4 = reinterpret_cast<const float4*>(A    + row * 1024)[tid];
    float4 b4 = reinterpret_cast<const float4*>(Bsrc + row * 1024)[tid];
    float x[4] = {a4.x + b4.x, a4.y + b4.y, a4.z + b4.z, a4.w + b4.w};

    float s = x[0] + x[1] + x[2] + x[3];
    s = blockRedSum(s, red);
    const float mu = s * (1.f / 1024.f);

    float vs = 0.f;
#pragma unroll
    for (int i = 0; i < 4; i++) { float d = x[i] - mu; vs += d * d; }
    vs = blockRedSum(vs, red);
    const float inv = rsqrtf(vs * (1.f / 1024.f) + 1e-5f);

    float4 g4 = reinterpret_cast<const float4*>(g)[tid];
    float4 e4 = reinterpret_cast<const float4*>(bet)[tid];
    float o[4];
    o[0] = (x[0] - mu) * inv * g4.x + e4.x;
    o[1] = (x[1] - mu) * inv * g4.y + e4.y;
    o[2] = (x[2] - mu) * inv * g4.z + e4.z;
    o[3] = (x[3] - mu) * inv * g4.w + e4.w;

    if (outF)
        reinterpret_cast<float4*>(outF + row * 1024)[tid] =
            make_float4(o[0], o[1], o[2], o[3]);
    if (outH) {
        __half2* oh = reinterpret_cast<__half2*>(outH + row * 1024);
        oh[2 * tid]     = __floats2half2_rn(o[0], o[1]);
        oh[2 * tid + 1] = __floats2half2_rn(o[2], o[3]);
    }
}

// ---------------- driver ---------------------------------------------------------
extern "C" void kernel_launch(void* const* d_in, const int* in_sizes, int n_in,
                              void* d_out, int out_size)
{
    const float* base   = (const float*)d_in[0];
    const float* fusion = (const float*)d_in[1];
    const float* Wq     = (const float*)d_in[2];
    const float* Wk     = (const float*)d_in[3];
    const float* Wv     = (const float*)d_in[4];
    const float* Wo     = (const float*)d_in[5];
    const float* g1     = (const float*)d_in[6];
    const float* b1     = (const float*)d_in[7];
    const float* g2     = (const float*)d_in[8];
    const float* b2     = (const float*)d_in[9];
    const float* fc1_w  = (const float*)d_in[10];
    const float* fc1_b  = (const float*)d_in[11];
    const float* fc2_w  = (const float*)d_in[12];
    const float* fc2_b  = (const float*)d_in[13];
    const float* rw     = (const float*)d_in[14];
    const float* rbias  = (const float*)d_in[15];
    const float* alphap = (const float*)d_in[16];

    float* outf = (float*)d_out;
    float* outm = outf + (long)B_ * TQ_ * D_;

    __half *baseh, *fush, *qh, *kh, *vh, *aoh, *xh, *h1h, *yh, *wh;
    float *x, *wo, *ff;
    cudaGetSymbolAddress((void**)&baseh, g_baseh);
    cudaGetSymbolAddress((void**)&fush,  g_fush);
    cudaGetSymbolAddress((void**)&qh,  g_qh);
    cudaGetSymbolAddress((void**)&kh,  g_kh);
    cudaGetSymbolAddress((void**)&vh,  g_vh);
    cudaGetSymbolAddress((void**)&aoh, g_aoh);
    cudaGetSymbolAddress((void**)&xh,  g_xh);
    cudaGetSymbolAddress((void**)&h1h, g_h1h);
    cudaGetSymbolAddress((void**)&yh,  g_yh);
    cudaGetSymbolAddress((void**)&wh,  g_wh);
    cudaGetSymbolAddress((void**)&x,   g_x);
    cudaGetSymbolAddress((void**)&wo,  g_wo);
    cudaGetSymbolAddress((void**)&ff,  g_ff);

    cudaFuncSetAttribute(gemm_h,
                         cudaFuncAttributeMaxDynamicSharedMemorySize, GEMMH_SMEM);
    cudaFuncSetAttribute(fattn_k,
                         cudaFuncAttributeMaxDynamicSharedMemorySize, FA_SMEM);

    const dim3 blk(256);
    const dim3 gBig(D_ / 128, (B_ * TQ_) / 128, 1);
    const long WN = 1024 * 1024;
    const int act4 = (B_ * TQ_ * D_) / 4;
    const int w4 = (int)(WN / 4);
    const int RB = 256;

    conv_h_k<<<(act4 + RB - 1) / RB, RB>>>(base,   baseh, act4);
    conv_h_k<<<(act4 + RB - 1) / RB, RB>>>(fusion, fush,  act4);
    const float* Ws[7] = {Wq, Wk, Wv, Wo, fc1_w, fc2_w, rw};
    for (int i = 0; i < 7; i++)
        conv_h_k<<<(w4 + RB - 1) / RB, RB>>>(Ws[i], wh + (long)i * WN, w4);
    const __half *WqH = wh, *WkH = wh + WN, *WvH = wh + 2*WN, *WoH = wh + 3*WN,
                 *f1H = wh + 4*WN, *f2H = wh + 5*WN, *rwH = wh + 6*WN;

    // Q/K/V projections (fp16 out)
    gemm_h<<<gBig, blk, GEMMH_SMEM>>>(baseh, WqH, qh, D_, D_, D_, D_, 1.f, nullptr, 8);
    gemm_h<<<gBig, blk, GEMMH_SMEM>>>(fush,  WkH, kh, D_, D_, D_, D_, 1.f, nullptr, 8);
    gemm_h<<<gBig, blk, GEMMH_SMEM>>>(fush,  WvH, vh, D_, D_, D_, D_, 1.f, nullptr, 8);

    // fused attention: masked (fp32) + ao (fp16)
    fattn_k<<<dim3(TQ_ / 16, B_ * H_), blk, FA_SMEM>>>(qh, kh, vh, outm, aoh, alphap);

    // O projection (fp32 out -> LN1)
    gemm_h<<<gBig, blk, GEMMH_SMEM>>>(aoh, WoH, wo, D_, D_, D_, D_, 1.f, nullptr, 0);

    // x = LN(base + wo): fp32 -> x, fp16 -> xh
    add_ln_k<<<B_ * TQ_, blk>>>(base, wo, g1, b1, x, xh);

    // FFN
    gemm_h<<<gBig, blk, GEMMH_SMEM>>>(xh,  f1H, h1h, D_, D_, D_, D_, 1.f, fc1_b, 11);
    gemm_h<<<gBig, blk, GEMMH_SMEM>>>(h1h, f2H, ff,  D_, D_, D_, D_, 1.f, fc2_b, 3);

    // y = LN(x + ff): fp16 -> yh
    add_ln_k<<<B_ * TQ_, blk>>>(x, ff, g2, b2, nullptr, yh);

    // final = y rw^T + rb (fp32 out)
    gemm_h<<<gBig, blk, GEMMH_SMEM>>>(yh, rwH, outf, D_, D_, D_, D_, 1.f, rbias, 1);
}

// round 9
// speedup vs baseline: 2.0298x; 1.1190x over previous
#include <cuda_runtime.h>
#include <cuda_fp16.h>
#include <math.h>
#include <stdint.h>

#define B_  8
#define TQ_ 1024
#define TK_ 1024
#define D_  1024
#define H_  16
#define HD_ 64

#define KCH 64
#define HPITCH 144
#define A_STAGE_B (128 * HPITCH)
#define GEMMH_SMEM (2 * 2 * A_STAGE_B)

// fused attention smem layout (32 queries / CTA)
#define FA_PITCH 144
#define FA_KVBUF (1024 * FA_PITCH)             // 147456 (K, later V)
#define FA_QOFF  FA_KVBUF                      // Q: 32 rows x 144B
#define FA_ORED  (FA_KVBUF + 32 * FA_PITCH)    // 152064
#define FA_OROW  68                            // padded row stride (words)
#define FA_OWARP (32 * FA_OROW)                // 2176 words / warp
#define FA_SMEM  (FA_ORED + 8 * FA_OWARP * 4)  // 152064 + 69632 = 221696

// ---------------- scratch -------------------------------------------------------
__device__ __half g_baseh[B_*TQ_*D_];
__device__ __half g_fush [B_*TK_*D_];
__device__ __half g_qh[B_*TQ_*D_];
__device__ __half g_kh[B_*TK_*D_];
__device__ __half g_vh[B_*TK_*D_];
__device__ __half g_aoh[B_*TQ_*D_];
__device__ __half g_xh [B_*TQ_*D_];
__device__ __half g_h1h[B_*TQ_*D_];
__device__ __half g_yh [B_*TQ_*D_];
__device__ __half g_wh [7*1024*1024];
__device__ float  g_x  [B_*TQ_*D_];
__device__ float  g_wo [B_*TQ_*D_];
__device__ float  g_ff [B_*TQ_*D_];

// ---------------- helpers -------------------------------------------------------
__device__ __forceinline__ void mma_f16(float* c,
                                        uint32_t a0, uint32_t a1, uint32_t a2, uint32_t a3,
                                        uint32_t b0, uint32_t b1) {
    asm volatile(
        "mma.sync.aligned.m16n8k16.row.col.f32.f16.f16.f32 "
        "{%0,%1,%2,%3}, {%4,%5,%6,%7}, {%8,%9}, {%0,%1,%2,%3};"
        : "+f"(c[0]), "+f"(c[1]), "+f"(c[2]), "+f"(c[3])
        : "r"(a0), "r"(a1), "r"(a2), "r"(a3), "r"(b0), "r"(b1));
}
__device__ __forceinline__ void ldmx4(uint32_t* r, uint32_t addr) {
    asm volatile("ldmatrix.sync.aligned.m8n8.x4.shared.b16 {%0,%1,%2,%3}, [%4];"
                 : "=r"(r[0]), "=r"(r[1]), "=r"(r[2]), "=r"(r[3]) : "r"(addr));
}
__device__ __forceinline__ void ldmx4t(uint32_t* r, uint32_t addr) {
    asm volatile("ldmatrix.sync.aligned.m8n8.x4.trans.shared.b16 {%0,%1,%2,%3}, [%4];"
                 : "=r"(r[0]), "=r"(r[1]), "=r"(r[2]), "=r"(r[3]) : "r"(addr));
}
__device__ __forceinline__ void cpa16(uint32_t smem_dst, const void* gsrc) {
    asm volatile("cp.async.cg.shared.global [%0], [%1], 16;"
                 :: "r"(smem_dst), "l"(gsrc));
}
__device__ __forceinline__ uint32_t smem_u32(const void* p) {
    uint32_t a;
    asm("{ .reg .u64 t; cvta.to.shared.u64 t, %1; cvt.u32.u64 %0, t; }" : "=r"(a) : "l"(p));
    return a;
}
__device__ __forceinline__ uint32_t packh2(float a, float b) {
    uint32_t r;
    asm("cvt.rn.f16x2.f32 %0, %2, %1;" : "=r"(r) : "f"(a), "f"(b));
    return r;   // lo = a, hi = b
}

// ---------------- reductions (block) --------------------------------------------
__device__ __forceinline__ float warpRedSum(float v) {
#pragma unroll
    for (int o = 16; o > 0; o >>= 1) v += __shfl_xor_sync(0xffffffffu, v, o);
    return v;
}
__device__ __forceinline__ float blockRedSum(float v, float* red) {
    v = warpRedSum(v);
    if ((threadIdx.x & 31) == 0) red[threadIdx.x >> 5] = v;
    __syncthreads();
    if (threadIdx.x < 32) {
        float x = (threadIdx.x < (blockDim.x >> 5)) ? red[threadIdx.x] : 0.f;
        x = warpRedSum(x);
        if (threadIdx.x == 0) red[0] = x;
    }
    __syncthreads();
    float r = red[0];
    __syncthreads();
    return r;
}

// ---------------- f32 -> f16 converts --------------------------------------------
__global__ void __launch_bounds__(256)
conv_h_k(const float* __restrict__ in, __half* __restrict__ out, int n4)
{
    int i = blockIdx.x * 256 + threadIdx.x;
    if (i < n4) {
        float4 v = reinterpret_cast<const float4*>(in)[i];
        __half2* o = reinterpret_cast<__half2*>(out);
        o[2 * i]     = __floats2half2_rn(v.x, v.y);
        o[2 * i + 1] = __floats2half2_rn(v.z, v.w);
    }
}
// 7 weights (1M f32 each) -> contiguous half dst, one launch
__global__ void __launch_bounds__(256)
conv_w_k(const float* s0, const float* s1, const float* s2, const float* s3,
         const float* s4, const float* s5, const float* s6, __half* __restrict__ out)
{
    const int i = blockIdx.x * 256 + threadIdx.x;     // float4 index, 7 * 262144 total
    const int wsel = i >> 18;
    const int off  = i & 0x3FFFF;
    const float* src = (wsel == 0) ? s0 : (wsel == 1) ? s1 : (wsel == 2) ? s2 :
                       (wsel == 3) ? s3 : (wsel == 4) ? s4 : (wsel == 5) ? s5 : s6;
    float4 v = reinterpret_cast<const float4*>(src)[off];
    __half2* o = reinterpret_cast<__half2*>(out);
    o[2 * i]     = __floats2half2_rn(v.x, v.y);
    o[2 * i + 1] = __floats2half2_rn(v.z, v.w);
}

// ============ FP16 GEMM (R6-validated, unchanged) ==============================
__global__ void __launch_bounds__(256, 2)
gemm_h(const __half* __restrict__ A, const __half* __restrict__ Bm,
       void* __restrict__ Cv, int Kd, int lda, int ldb, int ldc,
       float alpha, const float* __restrict__ bias, int mode)
{
    extern __shared__ char smbuf[];
    const uint32_t aBase = smem_u32(smbuf);
    const uint32_t bBase = aBase + 2 * A_STAGE_B;

    const __half* Ab = A;
    const __half* Bb = Bm;

    const int tid   = threadIdx.x;
    const int m0    = blockIdx.y * 128;
    const int n0    = blockIdx.x * 128;
    const int warp  = tid >> 5;
    const int lane  = tid & 31;
    const int warpM = warp & 1;
    const int warpN = warp >> 1;
    const int g     = lane >> 2;
    const int tg    = lane & 3;

    const int lr  = tid >> 3;
    const int seg = (tid & 7) * 8;

    const uint32_t aFragOff =
        (uint32_t)((warpM * 64 + (lane & 15)) * HPITCH + (lane >> 4) * 16);
    const uint32_t bFragOff =
        (uint32_t)(((warpN * 32 + (lane & 7) + ((lane >> 4) & 1) * 8)) * HPITCH
                   + ((lane >> 3) & 1) * 16);
    const uint32_t MT_STRIDE = 16 * HPITCH;

    float acc[4][4][4];
#pragma unroll
    for (int mt = 0; mt < 4; mt++)
#pragma unroll
        for (int nt = 0; nt < 4; nt++)
#pragma unroll
            for (int r = 0; r < 4; r++) acc[mt][nt][r] = 0.f;

#pragma unroll
    for (int i = 0; i < 4; i++) {
        const int r = lr + i * 32;
        cpa16(aBase + (uint32_t)(r * HPITCH + seg * 2), &Ab[(long)(m0 + r) * lda + seg]);
        cpa16(bBase + (uint32_t)(r * HPITCH + seg * 2), &Bb[(long)(n0 + r) * ldb + seg]);
    }
    asm volatile("cp.async.commit_group;");

    for (int k0 = 0; k0 < Kd; k0 += KCH) {
        const int st = (k0 / KCH) & 1;
        if (k0 + KCH < Kd) {
            const int sn = st ^ 1;
            const uint32_t aOff = aBase + (uint32_t)(sn * A_STAGE_B);
            const uint32_t bOff = bBase + (uint32_t)(sn * A_STAGE_B);
#pragma unroll
            for (int i = 0; i < 4; i++) {
                const int r = lr + i * 32;
                cpa16(aOff + (uint32_t)(r * HPITCH + seg * 2),
                      &Ab[(long)(m0 + r) * lda + k0 + KCH + seg]);
                cpa16(bOff + (uint32_t)(r * HPITCH + seg * 2),
                      &Bb[(long)(n0 + r) * ldb + k0 + KCH + seg]);
            }
        }
        asm volatile("cp.async.commit_group;");
        asm volatile("cp.async.wait_group 1;");
        __syncthreads();

        const uint32_t aSt = aBase + (uint32_t)(st * A_STAGE_B) + aFragOff;
        const uint32_t bSt = bBase + (uint32_t)(st * A_STAGE_B) + bFragOff;
#pragma unroll
        for (int ks = 0; ks < 4; ks++) {
            uint32_t af[4][4], bf[4][2];
#pragma unroll
            for (int mt = 0; mt < 4; mt++)
                ldmx4(af[mt], aSt + mt * MT_STRIDE + ks * 32);
#pragma unroll
            for (int p = 0; p < 2; p++) {
                uint32_t t[4];
                ldmx4(t, bSt + p * MT_STRIDE + ks * 32);
                bf[2 * p][0] = t[0]; bf[2 * p][1] = t[1];
                bf[2 * p + 1][0] = t[2]; bf[2 * p + 1][1] = t[3];
            }
#pragma unroll
            for (int mt = 0; mt < 4; mt++)
#pragma unroll
                for (int nt = 0; nt < 4; nt++)
                    mma_f16(acc[mt][nt], af[mt][0], af[mt][1], af[mt][2], af[mt][3],
                            bf[nt][0], bf[nt][1]);
        }
        __syncthreads();
    }

#pragma unroll
    for (int mt = 0; mt < 4; mt++) {
#pragma unroll
        for (int nt = 0; nt < 4; nt++) {
            const long row = m0 + warpM * 64 + mt * 16 + g;
            const int  col = n0 + warpN * 32 + nt * 8 + 2 * tg;
            float v0 = acc[mt][nt][0] * alpha;
            float v1 = acc[mt][nt][1] * alpha;
            float v2 = acc[mt][nt][2] * alpha;
            float v3 = acc[mt][nt][3] * alpha;
            if (mode & 1) {
                const float bb0 = bias[col], bb1 = bias[col + 1];
                v0 += bb0; v1 += bb1; v2 += bb0; v3 += bb1;
            }
            if (mode & 2) {
                v0 = v0 / (1.f + expf(-v0));
                v1 = v1 / (1.f + expf(-v1));
                v2 = v2 / (1.f + expf(-v2));
                v3 = v3 / (1.f + expf(-v3));
            }
            if (mode & 8) {
                __half* Ch = (__half*)Cv;
                *reinterpret_cast<__half2*>(&Ch[row * ldc + col]) = __floats2half2_rn(v0, v1);
                *reinterpret_cast<__half2*>(&Ch[(row + 8) * ldc + col]) = __floats2half2_rn(v2, v3);
            } else {
                float* Cf = (float*)Cv;
                *reinterpret_cast<float2*>(&Cf[row * ldc + col])       = make_float2(v0, v1);
                *reinterpret_cast<float2*>(&Cf[(row + 8) * ldc + col]) = make_float2(v2, v3);
            }
        }
    }
}

// ============ Fused attention (32 queries / CTA) ==============================
// Grid: (TQ/32, B*H). 256 thr. Warp w owns keys [w*128, w*128+128).
__global__ void __launch_bounds__(256, 1)
fattn_k(const __half* __restrict__ Qg, const __half* __restrict__ Kg,
        const __half* __restrict__ Vg, float* __restrict__ maskedG,
        __half* __restrict__ Og, const float* __restrict__ alphap)
{
    extern __shared__ char smc[];
    const uint32_t kvB = smem_u32(smc);
    const uint32_t qB  = kvB + FA_QOFF;
    float* Ored = reinterpret_cast<float*>(smc + FA_ORED);
    __shared__ float redm[256];
    __shared__ float redf[32];

    const int tid  = threadIdx.x;
    const int w    = tid >> 5, lane = tid & 31;
    const int g    = lane >> 2, tg = lane & 3;
    const int m0   = blockIdx.x * 32;
    const int z    = blockIdx.y;
    const long zb  = z >> 4, zh = z & 15;

    const __half* Qb = Qg + zb * (long)(TQ_ * D_) + zh * HD_;
    const __half* Kb = Kg + zb * (long)(TK_ * D_) + zh * HD_;
    const __half* Vb = Vg + zb * (long)(TK_ * D_) + zh * HD_;

    // ---- load Q (32x64) + K (1024x64) ----
    {
        const int r = tid >> 3, s = tid & 7;
        cpa16(qB + (uint32_t)(r * FA_PITCH + s * 16), Qb + (long)(m0 + r) * D_ + s * 8);
    }
#pragma unroll
    for (int i = 0; i < 32; i++) {
        const int idx = i * 256 + tid;
        const int r = idx >> 3, s = idx & 7;
        cpa16(kvB + (uint32_t)(r * FA_PITCH + s * 16), Kb + (long)r * D_ + s * 8);
    }
    asm volatile("cp.async.commit_group;");
    asm volatile("cp.async.wait_group 0;");
    __syncthreads();

    // ---- QK^T: acc[mt][nt][r], mt = 16-row tile, nt = 8-col tile ----
    float acc[2][16][4];
#pragma unroll
    for (int mt = 0; mt < 2; mt++)
#pragma unroll
        for (int nt = 0; nt < 16; nt++)
#pragma unroll
            for (int r = 0; r < 4; r++) acc[mt][nt][r] = 0.f;

    const uint32_t aOff0 = qB + (uint32_t)((lane & 15) * FA_PITCH + (lane >> 4) * 16);
    const uint32_t aOff1 = aOff0 + 16 * FA_PITCH;
    const uint32_t bOff = kvB + (uint32_t)((w * 128 + (lane & 7) + ((lane >> 4) & 1) * 8) * FA_PITCH
                                           + ((lane >> 3) & 1) * 16);
#pragma unroll
    for (int ks = 0; ks < 4; ks++) {
        uint32_t a0[4], a1[4];
        ldmx4(a0, aOff0 + ks * 32);
        ldmx4(a1, aOff1 + ks * 32);
#pragma unroll
        for (int nt2 = 0; nt2 < 8; nt2++) {
            uint32_t t[4];
            ldmx4(t, bOff + (uint32_t)(nt2 * 16 * FA_PITCH) + ks * 32);
            mma_f16(acc[0][2 * nt2],     a0[0], a0[1], a0[2], a0[3], t[0], t[1]);
            mma_f16(acc[0][2 * nt2 + 1], a0[0], a0[1], a0[2], a0[3], t[2], t[3]);
            mma_f16(acc[1][2 * nt2],     a1[0], a1[1], a1[2], a1[3], t[0], t[1]);
            mma_f16(acc[1][2 * nt2 + 1], a1[0], a1[1], a1[2], a1[3], t[2], t[3]);
        }
    }
    __syncthreads();                 // all warps done reading K

    // ---- start V load into the same buffer ----
#pragma unroll
    for (int i = 0; i < 32; i++) {
        const int idx = i * 256 + tid;
        const int r = idx >> 3, s = idx & 7;
        cpa16(kvB + (uint32_t)(r * FA_PITCH + s * 16), Vb + (long)r * D_ + s * 8);
    }
    asm volatile("cp.async.commit_group;");

    // ---- scale ----
#pragma unroll
    for (int mt = 0; mt < 2; mt++)
#pragma unroll
        for (int nt = 0; nt < 16; nt++)
#pragma unroll
            for (int r = 0; r < 4; r++) acc[mt][nt][r] *= 0.125f;

    // ---- softmax1: row max (4 rows/thread: mt*16+g, mt*16+8+g) ----
    float rmax[2][2];
#pragma unroll
    for (int mt = 0; mt < 2; mt++) {
        float lo = -1e30f, hi = -1e30f;
#pragma unroll
        for (int nt = 0; nt < 16; nt++) {
            lo = fmaxf(lo, fmaxf(acc[mt][nt][0], acc[mt][nt][1]));
            hi = fmaxf(hi, fmaxf(acc[mt][nt][2], acc[mt][nt][3]));
        }
        lo = fmaxf(lo, __shfl_xor_sync(~0u, lo, 1)); lo = fmaxf(lo, __shfl_xor_sync(~0u, lo, 2));
        hi = fmaxf(hi, __shfl_xor_sync(~0u, hi, 1)); hi = fmaxf(hi, __shfl_xor_sync(~0u, hi, 2));
        rmax[mt][0] = lo; rmax[mt][1] = hi;
    }
    if (tg == 0) {
        redm[w * 32 + g]      = rmax[0][0];
        redm[w * 32 + 8 + g]  = rmax[0][1];
        redm[w * 32 + 16 + g] = rmax[1][0];
        redm[w * 32 + 24 + g] = rmax[1][1];
    }
    __syncthreads();
    if (tid < 32) {
        float m = -1e30f;
#pragma unroll
        for (int ww = 0; ww < 8; ww++) m = fmaxf(m, redm[ww * 32 + tid]);
        redf[tid] = m;
    }
    __syncthreads();
    rmax[0][0] = redf[g]; rmax[0][1] = redf[8 + g];
    rmax[1][0] = redf[16 + g]; rmax[1][1] = redf[24 + g];
    __syncthreads();

    // ---- exp + row sum ----
    float rsum[2][2];
#pragma unroll
    for (int mt = 0; mt < 2; mt++) {
        float slo = 0.f, shi = 0.f;
#pragma unroll
        for (int nt = 0; nt < 16; nt++) {
            acc[mt][nt][0] = expf(acc[mt][nt][0] - rmax[mt][0]);
            acc[mt][nt][1] = expf(acc[mt][nt][1] - rmax[mt][0]);
            acc[mt][nt][2] = expf(acc[mt][nt][2] - rmax[mt][1]);
            acc[mt][nt][3] = expf(acc[mt][nt][3] - rmax[mt][1]);
            slo += acc[mt][nt][0] + acc[mt][nt][1];
            shi += acc[mt][nt][2] + acc[mt][nt][3];
        }
        slo += __shfl_xor_sync(~0u, slo, 1); slo += __shfl_xor_sync(~0u, slo, 2);
        shi += __shfl_xor_sync(~0u, shi, 1); shi += __shfl_xor_sync(~0u, shi, 2);
        rsum[mt][0] = slo; rsum[mt][1] = shi;
    }
    if (tg == 0) {
        redm[w * 32 + g]      = rsum[0][0];
        redm[w * 32 + 8 + g]  = rsum[0][1];
        redm[w * 32 + 16 + g] = rsum[1][0];
        redm[w * 32 + 24 + g] = rsum[1][1];
    }
    __syncthreads();
    if (tid < 32) {
        float s = 0.f;
#pragma unroll
        for (int ww = 0; ww < 8; ww++) s += redm[ww * 32 + tid];
        redf[tid] = s;
    }
    __syncthreads();
    float inv1[2][2];
    inv1[0][0] = 1.f / redf[g]; inv1[0][1] = 1.f / redf[8 + g];
    inv1[1][0] = 1.f / redf[16 + g]; inv1[1][1] = 1.f / redf[24 + g];
    __syncthreads();

    // ---- attn, mask, write masked ----
    const float alpha = *alphap;
#pragma unroll
    for (int mt = 0; mt < 2; mt++) {
        float* m0p = maskedG + (long)z * TQ_ * TK_
                   + (long)(m0 + mt * 16 + g) * 1024 + w * 128 + 2 * tg;
        float* m1p = m0p + 8L * 1024;
#pragma unroll
        for (int nt = 0; nt < 16; nt++) {
            float a0 = acc[mt][nt][0] * inv1[mt][0]; if (a0 < alpha) a0 = 0.f;
            float a1 = acc[mt][nt][1] * inv1[mt][0]; if (a1 < alpha) a1 = 0.f;
            float a2 = acc[mt][nt][2] * inv1[mt][1]; if (a2 < alpha) a2 = 0.f;
            float a3 = acc[mt][nt][3] * inv1[mt][1]; if (a3 < alpha) a3 = 0.f;
            *reinterpret_cast<float2*>(m0p + nt * 8) = make_float2(a0, a1);
            *reinterpret_cast<float2*>(m1p + nt * 8) = make_float2(a2, a3);
            acc[mt][nt][0] = a0; acc[mt][nt][1] = a1; acc[mt][nt][2] = a2; acc[mt][nt][3] = a3;
        }
    }

    // ---- softmax2: max ----
#pragma unroll
    for (int mt = 0; mt < 2; mt++) {
        float lo = -1e30f, hi = -1e30f;
#pragma unroll
        for (int nt = 0; nt < 16; nt++) {
            lo = fmaxf(lo, fmaxf(acc[mt][nt][0], acc[mt][nt][1]));
            hi = fmaxf(hi, fmaxf(acc[mt][nt][2], acc[mt][nt][3]));
        }
        lo = fmaxf(lo, __shfl_xor_sync(~0u, lo, 1)); lo = fmaxf(lo, __shfl_xor_sync(~0u, lo, 2));
        hi = fmaxf(hi, __shfl_xor_sync(~0u, hi, 1)); hi = fmaxf(hi, __shfl_xor_sync(~0u, hi, 2));
        rmax[mt][0] = lo; rmax[mt][1] = hi;
    }
    if (tg == 0) {
        redm[w * 32 + g]      = rmax[0][0];
        redm[w * 32 + 8 + g]  = rmax[0][1];
        redm[w * 32 + 16 + g] = rmax[1][0];
        redm[w * 32 + 24 + g] = rmax[1][1];
    }
    __syncthreads();
    if (tid < 32) {
        float m = -1e30f;
#pragma unroll
        for (int ww = 0; ww < 8; ww++) m = fmaxf(m, redm[ww * 32 + tid]);
        redf[tid] = m;
    }
    __syncthreads();
    rmax[0][0] = redf[g]; rmax[0][1] = redf[8 + g];
    rmax[1][0] = redf[16 + g]; rmax[1][1] = redf[24 + g];
    __syncthreads();

    // ---- softmax2: exp + sum ----
#pragma unroll
    for (int mt = 0; mt < 2; mt++) {
        float slo = 0.f, shi = 0.f;
#pragma unroll
        for (int nt = 0; nt < 16; nt++) {
            acc[mt][nt][0] = expf(acc[mt][nt][0] - rmax[mt][0]);
            acc[mt][nt][1] = expf(acc[mt][nt][1] - rmax[mt][0]);
            acc[mt][nt][2] = expf(acc[mt][nt][2] - rmax[mt][1]);
            acc[mt][nt][3] = expf(acc[mt][nt][3] - rmax[mt][1]);
            slo += acc[mt][nt][0] + acc[mt][nt][1];
            shi += acc[mt][nt][2] + acc[mt][nt][3];
        }
        slo += __shfl_xor_sync(~0u, slo, 1); slo += __shfl_xor_sync(~0u, slo, 2);
        shi += __shfl_xor_sync(~0u, shi, 1); shi += __shfl_xor_sync(~0u, shi, 2);
        rsum[mt][0] = slo; rsum[mt][1] = shi;
    }
    if (tg == 0) {
        redm[w * 32 + g]      = rsum[0][0];
        redm[w * 32 + 8 + g]  = rsum[0][1];
        redm[w * 32 + 16 + g] = rsum[1][0];
        redm[w * 32 + 24 + g] = rsum[1][1];
    }
    __syncthreads();
    if (tid < 32) {
        float s = 0.f;
#pragma unroll
        for (int ww = 0; ww < 8; ww++) s += redm[ww * 32 + tid];
        redf[tid] = s;
    }
    __syncthreads();
    float inv2[2][2];
    inv2[0][0] = 1.f / redf[g]; inv2[0][1] = 1.f / redf[8 + g];
    inv2[1][0] = 1.f / redf[16 + g]; inv2[1][1] = 1.f / redf[24 + g];

    // ---- pack P to half2 (frees fp32 accs) ----
    uint32_t pk[2][16][2];
#pragma unroll
    for (int mt = 0; mt < 2; mt++)
#pragma unroll
        for (int nt = 0; nt < 16; nt++) {
            pk[mt][nt][0] = packh2(acc[mt][nt][0] * inv2[mt][0],
                                   acc[mt][nt][1] * inv2[mt][0]);
            pk[mt][nt][1] = packh2(acc[mt][nt][2] * inv2[mt][1],
                                   acc[mt][nt][3] * inv2[mt][1]);
        }

    // ---- wait for V, then P@V ----
    asm volatile("cp.async.wait_group 0;");
    __syncthreads();

    float o[2][8][4];
#pragma unroll
    for (int mt = 0; mt < 2; mt++)
#pragma unroll
        for (int nt = 0; nt < 8; nt++)
#pragma unroll
            for (int r = 0; r < 4; r++) o[mt][nt][r] = 0.f;

    const uint32_t vOff = kvB + (uint32_t)(((lane & 7) + ((lane >> 3) & 1) * 8) * FA_PITCH
                                           + (lane >> 4) * 16);
#pragma unroll
    for (int s = 0; s < 8; s++) {
        const uint32_t vRow = vOff + (uint32_t)((w * 128 + s * 16) * FA_PITCH);
#pragma unroll
        for (int p = 0; p < 4; p++) {
            uint32_t t[4];
            ldmx4t(t, vRow + p * 32);
#pragma unroll
            for (int mt = 0; mt < 2; mt++) {
                mma_f16(o[mt][2 * p],     pk[mt][2 * s][0], pk[mt][2 * s][1],
                        pk[mt][2 * s + 1][0], pk[mt][2 * s + 1][1], t[0], t[1]);
                mma_f16(o[mt][2 * p + 1], pk[mt][2 * s][0], pk[mt][2 * s][1],
                        pk[mt][2 * s + 1][0], pk[mt][2 * s + 1][1], t[2], t[3]);
            }
        }
    }

    // ---- cross-warp O reduce via smem ----
#pragma unroll
    for (int mt = 0; mt < 2; mt++)
#pragma unroll
        for (int nt = 0; nt < 8; nt++) {
            const int c = nt * 8 + 2 * tg;
            const int r0 = mt * 16 + g, r1 = mt * 16 + 8 + g;
            Ored[w * FA_OWARP + r0 * FA_OROW + c]     = o[mt][nt][0];
            Ored[w * FA_OWARP + r0 * FA_OROW + c + 1] = o[mt][nt][1];
            Ored[w * FA_OWARP + r1 * FA_OROW + c]     = o[mt][nt][2];
            Ored[w * FA_OWARP + r1 * FA_OROW + c + 1] = o[mt][nt][3];
        }
    __syncthreads();
    {
        const int e = tid * 8;
        const int r = e >> 6, c = e & 63;
        float s[8];
#pragma unroll
        for (int j = 0; j < 8; j++) s[j] = 0.f;
#pragma unroll
        for (int ww = 0; ww < 8; ww++) {
            const float* p = &Ored[ww * FA_OWARP + r * FA_OROW + c];
#pragma unroll
            for (int j = 0; j < 8; j++) s[j] += p[j];
        }
        __half2* op = reinterpret_cast<__half2*>(
            Og + zb * (long)(TQ_ * D_) + (long)(m0 + r) * D_ + zh * HD_ + c);
#pragma unroll
        for (int j = 0; j < 4; j++)
            op[j] = __floats2half2_rn(s[2 * j], s[2 * j + 1]);
    }
}

// ---------------- LayerNorm(a + b) * g + beta ------------------------------------
__global__ void __launch_bounds__(256)
add_ln_k(const float* __restrict__ A, const float* __restrict__ Bsrc,
         const float* __restrict__ g, const float* __restrict__ bet,
         float* __restrict__ outF, __half* __restrict__ outH)
{
    __shared__ float red[32];
    const long row = blockIdx.x;
    const int tid = threadIdx.x;

    float4 a4 = reinterpret_cast<const float4*>(A    + row * 1024)[tid];
    float4 b4 = reinterpret_cast<const float4*>(Bsrc + row * 1024)[tid];
    float x[4] = {a4.x + b4.x, a4.y + b4.y, a4.z + b4.z, a4.w + b4.w};

    float s = x[0] + x[1] + x[2] + x[3];
    s = blockRedSum(s, red);
    const float mu = s * (1.f / 1024.f);

    float vs = 0.f;
#pragma unroll
    for (int i = 0; i < 4; i++) { float d = x[i] - mu; vs += d * d; }
    vs = blockRedSum(vs, red);
    const float inv = rsqrtf(vs * (1.f / 1024.f) + 1e-5f);

    float4 g4 = reinterpret_cast<const float4*>(g)[tid];
    float4 e4 = reinterpret_cast<const float4*>(bet)[tid];
    float o[4];
    o[0] = (x[0] - mu) * inv * g4.x + e4.x;
    o[1] = (x[1] - mu) * inv * g4.y + e4.y;
    o[2] = (x[2] - mu) * inv * g4.z + e4.z;
    o[3] = (x[3] - mu) * inv * g4.w + e4.w;

    if (outF)
        reinterpret_cast<float4*>(outF + row * 1024)[tid] =
            make_float4(o[0], o[1], o[2], o[3]);
    if (outH) {
        __half2* oh = reinterpret_cast<__half2*>(outH + row * 1024);
        oh[2 * tid]     = __floats2half2_rn(o[0], o[1]);
        oh[2 * tid + 1] = __floats2half2_rn(o[2], o[3]);
    }
}

// ---------------- driver ---------------------------------------------------------
extern "C" void kernel_launch(void* const* d_in, const int* in_sizes, int n_in,
                              void* d_out, int out_size)
{
    const float* base   = (const float*)d_in[0];
    const float* fusion = (const float*)d_in[1];
    const float* Wq     = (const float*)d_in[2];
    const float* Wk     = (const float*)d_in[3];
    const float* Wv     = (const float*)d_in[4];
    const float* Wo     = (const float*)d_in[5];
    const float* g1     = (const float*)d_in[6];
    const float* b1     = (const float*)d_in[7];
    const float* g2     = (const float*)d_in[8];
    const float* b2     = (const float*)d_in[9];
    const float* fc1_w  = (const float*)d_in[10];
    const float* fc1_b  = (const float*)d_in[11];
    const float* fc2_w  = (const float*)d_in[12];
    const float* fc2_b  = (const float*)d_in[13];
    const float* rw     = (const float*)d_in[14];
    const float* rbias  = (const float*)d_in[15];
    const float* alphap = (const float*)d_in[16];

    float* outf = (float*)d_out;
    float* outm = outf + (long)B_ * TQ_ * D_;

    __half *baseh, *fush, *qh, *kh, *vh, *aoh, *xh, *h1h, *yh, *wh;
    float *x, *wo, *ff;
    cudaGetSymbolAddress((void**)&baseh, g_baseh);
    cudaGetSymbolAddress((void**)&fush,  g_fush);
    cudaGetSymbolAddress((void**)&qh,  g_qh);
    cudaGetSymbolAddress((void**)&kh,  g_kh);
    cudaGetSymbolAddress((void**)&vh,  g_vh);
    cudaGetSymbolAddress((void**)&aoh, g_aoh);
    cudaGetSymbolAddress((void**)&xh,  g_xh);
    cudaGetSymbolAddress((void**)&h1h, g_h1h);
    cudaGetSymbolAddress((void**)&yh,  g_yh);
    cudaGetSymbolAddress((void**)&wh,  g_wh);
    cudaGetSymbolAddress((void**)&x,   g_x);
    cudaGetSymbolAddress((void**)&wo,  g_wo);
    cudaGetSymbolAddress((void**)&ff,  g_ff);

    cudaFuncSetAttribute(gemm_h,
                         cudaFuncAttributeMaxDynamicSharedMemorySize, GEMMH_SMEM);
    cudaFuncSetAttribute(fattn_k,
                         cudaFuncAttributeMaxDynamicSharedMemorySize, FA_SMEM);

    const dim3 blk(256);
    const dim3 gBig(D_ / 128, (B_ * TQ_) / 128, 1);
    const long WN = 1024 * 1024;
    const int act4 = (B_ * TQ_ * D_) / 4;
    const int RB = 256;

    // converts: base, fusion, all 7 weights in one launch
    conv_h_k<<<(act4 + RB - 1) / RB, RB>>>(base,   baseh, act4);
    conv_h_k<<<(act4 + RB - 1) / RB, RB>>>(fusion, fush,  act4);
    conv_w_k<<<7 * 262144 / RB, RB>>>(Wq, Wk, Wv, Wo, fc1_w, fc2_w, rw, wh);
    const __half *WqH = wh, *WkH = wh + WN, *WvH = wh + 2*WN, *WoH = wh + 3*WN,
                 *f1H = wh + 4*WN, *f2H = wh + 5*WN, *rwH = wh + 6*WN;

    // Q/K/V projections (fp16 out)
    gemm_h<<<gBig, blk, GEMMH_SMEM>>>(baseh, WqH, qh, D_, D_, D_, D_, 1.f, nullptr, 8);
    gemm_h<<<gBig, blk, GEMMH_SMEM>>>(fush,  WkH, kh, D_, D_, D_, D_, 1.f, nullptr, 8);
    gemm_h<<<gBig, blk, GEMMH_SMEM>>>(fush,  WvH, vh, D_, D_, D_, D_, 1.f, nullptr, 8);

    // fused attention: masked (fp32) + ao (fp16)
    fattn_k<<<dim3(TQ_ / 32, B_ * H_), blk, FA_SMEM>>>(qh, kh, vh, outm, aoh, alphap);

    // O projection (fp32 out -> LN1)
    gemm_h<<<gBig, blk, GEMMH_SMEM>>>(aoh, WoH, wo, D_, D_, D_, D_, 1.f, nullptr, 0);

    // x = LN(base + wo): fp32 -> x, fp16 -> xh
    add_ln_k<<<B_ * TQ_, blk>>>(base, wo, g1, b1, x, xh);

    // FFN
    gemm_h<<<gBig, blk, GEMMH_SMEM>>>(xh,  f1H, h1h, D_, D_, D_, D_, 1.f, fc1_b, 11);
    gemm_h<<<gBig, blk, GEMMH_SMEM>>>(h1h, f2H, ff,  D_, D_, D_, D_, 1.f, fc2_b, 3);

    // y = LN(x + ff): fp16 -> yh
    add_ln_k<<<B_ * TQ_, blk>>>(x, ff, g2, b2, nullptr, yh);

    // final = y rw^T + rb (fp32 out)
    gemm_h<<<gBig, blk, GEMMH_SMEM>>>(yh, rwH, outf, D_, D_, D_, D_, 1.f, rbias, 1);
}

// round 10
// speedup vs baseline: 2.0709x; 1.0203x over previous
#include <cuda_runtime.h>
#include <cuda_fp16.h>
#include <math.h>
#include <stdint.h>

#define B_  8
#define TQ_ 1024
#define TK_ 1024
#define D_  1024
#define H_  16
#define HD_ 64

#define KCH 64
#define HPITCH 144
#define A_STAGE_B (128 * HPITCH)          // 18432 B per 128x64h tile
#define NST 3
#define GEMMH_SMEM (NST * 2 * A_STAGE_B)  // 110592 B

// fused attention smem layout (32 queries / CTA)
#define FA_PITCH 144
#define FA_KVBUF (1024 * FA_PITCH)             // 147456 (K, later V)
#define FA_QOFF  FA_KVBUF                      // Q: 32 rows x 144B
#define FA_ORED  (FA_KVBUF + 32 * FA_PITCH)    // 152064
#define FA_OROW  68                            // padded row stride (words)
#define FA_OWARP (32 * FA_OROW)                // 2176 words / warp
#define FA_SMEM  (FA_ORED + 8 * FA_OWARP * 4)  // 221696

// ---------------- scratch -------------------------------------------------------
__device__ __half g_baseh[B_*TQ_*D_];
__device__ __half g_fush [B_*TK_*D_];
__device__ __half g_qh  [B_*TQ_*D_];
__device__ __half g_kvh [B_*TK_*2*D_];     // K | V interleaved per row (ld 2048)
__device__ __half g_aoh [B_*TQ_*D_];
__device__ __half g_xh  [B_*TQ_*D_];
__device__ __half g_h1h [B_*TQ_*D_];
__device__ __half g_yh  [B_*TQ_*D_];
__device__ __half g_wh  [7*1024*1024];
__device__ float  g_x   [B_*TQ_*D_];
__device__ float  g_wo  [B_*TQ_*D_];
__device__ float  g_ff  [B_*TQ_*D_];

// ---------------- helpers -------------------------------------------------------
__device__ __forceinline__ void mma_f16(float* c,
                                        uint32_t a0, uint32_t a1, uint32_t a2, uint32_t a3,
                                        uint32_t b0, uint32_t b1) {
    asm volatile(
        "mma.sync.aligned.m16n8k16.row.col.f32.f16.f16.f32 "
        "{%0,%1,%2,%3}, {%4,%5,%6,%7}, {%8,%9}, {%0,%1,%2,%3};"
        : "+f"(c[0]), "+f"(c[1]), "+f"(c[2]), "+f"(c[3])
        : "r"(a0), "r"(a1), "r"(a2), "r"(a3), "r"(b0), "r"(b1));
}
__device__ __forceinline__ void ldmx4(uint32_t* r, uint32_t addr) {
    asm volatile("ldmatrix.sync.aligned.m8n8.x4.shared.b16 {%0,%1,%2,%3}, [%4];"
                 : "=r"(r[0]), "=r"(r[1]), "=r"(r[2]), "=r"(r[3]) : "r"(addr));
}
__device__ __forceinline__ void ldmx4t(uint32_t* r, uint32_t addr) {
    asm volatile("ldmatrix.sync.aligned.m8n8.x4.trans.shared.b16 {%0,%1,%2,%3}, [%4];"
                 : "=r"(r[0]), "=r"(r[1]), "=r"(r[2]), "=r"(r[3]) : "r"(addr));
}
__device__ __forceinline__ void cpa16(uint32_t smem_dst, const void* gsrc) {
    asm volatile("cp.async.cg.shared.global [%0], [%1], 16;"
                 :: "r"(smem_dst), "l"(gsrc));
}
__device__ __forceinline__ uint32_t smem_u32(const void* p) {
    uint32_t a;
    asm("{ .reg .u64 t; cvta.to.shared.u64 t, %1; cvt.u32.u64 %0, t; }" : "=r"(a) : "l"(p));
    return a;
}
__device__ __forceinline__ uint32_t packh2(float a, float b) {
    uint32_t r;
    asm("cvt.rn.f16x2.f32 %0, %2, %1;" : "=r"(r) : "f"(a), "f"(b));
    return r;   // lo = a, hi = b
}

// ---------------- reductions (block) --------------------------------------------
__device__ __forceinline__ float warpRedSum(float v) {
#pragma unroll
    for (int o = 16; o > 0; o >>= 1) v += __shfl_xor_sync(0xffffffffu, v, o);
    return v;
}
__device__ __forceinline__ float blockRedSum(float v, float* red) {
    v = warpRedSum(v);
    if ((threadIdx.x & 31) == 0) red[threadIdx.x >> 5] = v;
    __syncthreads();
    if (threadIdx.x < 32) {
        float x = (threadIdx.x < (blockDim.x >> 5)) ? red[threadIdx.x] : 0.f;
        x = warpRedSum(x);
        if (threadIdx.x == 0) red[0] = x;
    }
    __syncthreads();
    float r = red[0];
    __syncthreads();
    return r;
}

// ---------------- f32 -> f16 converts --------------------------------------------
__global__ void __launch_bounds__(256)
conv_h_k(const float* __restrict__ in, __half* __restrict__ out, int n4)
{
    int i = blockIdx.x * 256 + threadIdx.x;
    if (i < n4) {
        float4 v = reinterpret_cast<const float4*>(in)[i];
        __half2* o = reinterpret_cast<__half2*>(out);
        o[2 * i]     = __floats2half2_rn(v.x, v.y);
        o[2 * i + 1] = __floats2half2_rn(v.z, v.w);
    }
}
__global__ void __launch_bounds__(256)
conv_w_k(const float* s0, const float* s1, const float* s2, const float* s3,
         const float* s4, const float* s5, const float* s6, __half* __restrict__ out)
{
    const int i = blockIdx.x * 256 + threadIdx.x;
    const int wsel = i >> 18;
    const int off  = i & 0x3FFFF;
    const float* src = (wsel == 0) ? s0 : (wsel == 1) ? s1 : (wsel == 2) ? s2 :
                       (wsel == 3) ? s3 : (wsel == 4) ? s4 : (wsel == 5) ? s5 : s6;
    float4 v = reinterpret_cast<const float4*>(src)[off];
    __half2* o = reinterpret_cast<__half2*>(out);
    o[2 * i]     = __floats2half2_rn(v.x, v.y);
    o[2 * i + 1] = __floats2half2_rn(v.z, v.w);
}

// ============ FP16 GEMM, 3-stage cp.async ring ================================
__global__ void __launch_bounds__(256, 2)
gemm_h(const __half* __restrict__ A, const __half* __restrict__ Bm,
       void* __restrict__ Cv, int Kd, int lda, int ldb, int ldc,
       float alpha, const float* __restrict__ bias, int mode)
{
    extern __shared__ char smbuf[];
    const uint32_t aBase = smem_u32(smbuf);
    const uint32_t bBase = aBase + NST * A_STAGE_B;

    const __half* Ab = A;
    const __half* Bb = Bm;

    const int tid   = threadIdx.x;
    const int m0    = blockIdx.y * 128;
    const int n0    = blockIdx.x * 128;
    const int warp  = tid >> 5;
    const int lane  = tid & 31;
    const int warpM = warp & 1;
    const int warpN = warp >> 1;
    const int g     = lane >> 2;
    const int tg    = lane & 3;

    const int lr  = tid >> 3;
    const int seg = (tid & 7) * 8;

    const uint32_t aFragOff =
        (uint32_t)((warpM * 64 + (lane & 15)) * HPITCH + (lane >> 4) * 16);
    const uint32_t bFragOff =
        (uint32_t)(((warpN * 32 + (lane & 7) + ((lane >> 4) & 1) * 8)) * HPITCH
                   + ((lane >> 3) & 1) * 16);
    const uint32_t MT_STRIDE = 16 * HPITCH;

    float acc[4][4][4];
#pragma unroll
    for (int mt = 0; mt < 4; mt++)
#pragma unroll
        for (int nt = 0; nt < 4; nt++)
#pragma unroll
            for (int r = 0; r < 4; r++) acc[mt][nt][r] = 0.f;

    const int nch = Kd / KCH;

    // prefetch chunks 0,1 into stages 0,1
#pragma unroll
    for (int c = 0; c < 2; c++) {
        const uint32_t aOff = aBase + (uint32_t)(c * A_STAGE_B);
        const uint32_t bOff = bBase + (uint32_t)(c * A_STAGE_B);
#pragma unroll
        for (int i = 0; i < 4; i++) {
            const int r = lr + i * 32;
            cpa16(aOff + (uint32_t)(r * HPITCH + seg * 2),
                  &Ab[(long)(m0 + r) * lda + c * KCH + seg]);
            cpa16(bOff + (uint32_t)(r * HPITCH + seg * 2),
                  &Bb[(long)(n0 + r) * ldb + c * KCH + seg]);
        }
        asm volatile("cp.async.commit_group;");
    }

    for (int c = 0; c < nch; c++) {
        asm volatile("cp.async.wait_group 1;");
        __syncthreads();

        const int pf = c + 2;
        if (pf < nch) {
            const int sn = pf % NST;
            const uint32_t aOff = aBase + (uint32_t)(sn * A_STAGE_B);
            const uint32_t bOff = bBase + (uint32_t)(sn * A_STAGE_B);
#pragma unroll
            for (int i = 0; i < 4; i++) {
                const int r = lr + i * 32;
                cpa16(aOff + (uint32_t)(r * HPITCH + seg * 2),
                      &Ab[(long)(m0 + r) * lda + pf * KCH + seg]);
                cpa16(bOff + (uint32_t)(r * HPITCH + seg * 2),
                      &Bb[(long)(n0 + r) * ldb + pf * KCH + seg]);
            }
        }
        asm volatile("cp.async.commit_group;");

        const int st = c % NST;
        const uint32_t aSt = aBase + (uint32_t)(st * A_STAGE_B) + aFragOff;
        const uint32_t bSt = bBase + (uint32_t)(st * A_STAGE_B) + bFragOff;
#pragma unroll
        for (int ks = 0; ks < 4; ks++) {
            uint32_t af[4][4], bf[4][2];
#pragma unroll
            for (int mt = 0; mt < 4; mt++)
                ldmx4(af[mt], aSt + mt * MT_STRIDE + ks * 32);
#pragma unroll
            for (int p = 0; p < 2; p++) {
                uint32_t t[4];
                ldmx4(t, bSt + p * MT_STRIDE + ks * 32);
                bf[2 * p][0] = t[0]; bf[2 * p][1] = t[1];
                bf[2 * p + 1][0] = t[2]; bf[2 * p + 1][1] = t[3];
            }
#pragma unroll
            for (int mt = 0; mt < 4; mt++)
#pragma unroll
                for (int nt = 0; nt < 4; nt++)
                    mma_f16(acc[mt][nt], af[mt][0], af[mt][1], af[mt][2], af[mt][3],
                            bf[nt][0], bf[nt][1]);
        }
    }

#pragma unroll
    for (int mt = 0; mt < 4; mt++) {
#pragma unroll
        for (int nt = 0; nt < 4; nt++) {
            const long row = m0 + warpM * 64 + mt * 16 + g;
            const int  col = n0 + warpN * 32 + nt * 8 + 2 * tg;
            float v0 = acc[mt][nt][0] * alpha;
            float v1 = acc[mt][nt][1] * alpha;
            float v2 = acc[mt][nt][2] * alpha;
            float v3 = acc[mt][nt][3] * alpha;
            if (mode & 1) {
                const float bb0 = bias[col], bb1 = bias[col + 1];
                v0 += bb0; v1 += bb1; v2 += bb0; v3 += bb1;
            }
            if (mode & 2) {
                v0 = v0 / (1.f + expf(-v0));
                v1 = v1 / (1.f + expf(-v1));
                v2 = v2 / (1.f + expf(-v2));
                v3 = v3 / (1.f + expf(-v3));
            }
            if (mode & 8) {
                __half* Ch = (__half*)Cv;
                *reinterpret_cast<__half2*>(&Ch[row * ldc + col]) = __floats2half2_rn(v0, v1);
                *reinterpret_cast<__half2*>(&Ch[(row + 8) * ldc + col]) = __floats2half2_rn(v2, v3);
            } else {
                float* Cf = (float*)Cv;
                *reinterpret_cast<float2*>(&Cf[row * ldc + col])       = make_float2(v0, v1);
                *reinterpret_cast<float2*>(&Cf[(row + 8) * ldc + col]) = make_float2(v2, v3);
            }
        }
    }
}

// ============ Fused attention (32 queries / CTA) ==============================
// K/V live in g_kvh with row stride 2048 (K at col 0, V at col 1024).
__global__ void __launch_bounds__(256, 1)
fattn_k(const __half* __restrict__ Qg, const __half* __restrict__ KVg,
        float* __restrict__ maskedG, __half* __restrict__ Og,
        const float* __restrict__ alphap)
{
    extern __shared__ char smc[];
    const uint32_t kvB = smem_u32(smc);
    const uint32_t qB  = kvB + FA_QOFF;
    float* Ored = reinterpret_cast<float*>(smc + FA_ORED);
    __shared__ float redm[256];
    __shared__ float redf[32];

    const int tid  = threadIdx.x;
    const int w    = tid >> 5, lane = tid & 31;
    const int g    = lane >> 2, tg = lane & 3;
    const int m0   = blockIdx.x * 32;
    const int z    = blockIdx.y;
    const long zb  = z >> 4, zh = z & 15;

    const __half* Qb = Qg  + zb * (long)(TQ_ * D_)   + zh * HD_;
    const __half* Kb = KVg + zb * (long)(TK_ * 2048) + zh * HD_;
    const __half* Vb = Kb + 1024;

    // ---- load Q (32x64) + K (1024x64) ----
    {
        const int r = tid >> 3, s = tid & 7;
        cpa16(qB + (uint32_t)(r * FA_PITCH + s * 16), Qb + (long)(m0 + r) * D_ + s * 8);
    }
#pragma unroll
    for (int i = 0; i < 32; i++) {
        const int idx = i * 256 + tid;
        const int r = idx >> 3, s = idx & 7;
        cpa16(kvB + (uint32_t)(r * FA_PITCH + s * 16), Kb + (long)r * 2048 + s * 8);
    }
    asm volatile("cp.async.commit_group;");
    asm volatile("cp.async.wait_group 0;");
    __syncthreads();

    // ---- QK^T ----
    float acc[2][16][4];
#pragma unroll
    for (int mt = 0; mt < 2; mt++)
#pragma unroll
        for (int nt = 0; nt < 16; nt++)
#pragma unroll
            for (int r = 0; r < 4; r++) acc[mt][nt][r] = 0.f;

    const uint32_t aOff0 = qB + (uint32_t)((lane & 15) * FA_PITCH + (lane >> 4) * 16);
    const uint32_t aOff1 = aOff0 + 16 * FA_PITCH;
    const uint32_t bOff = kvB + (uint32_t)((w * 128 + (lane & 7) + ((lane >> 4) & 1) * 8) * FA_PITCH
                                           + ((lane >> 3) & 1) * 16);
#pragma unroll
    for (int ks = 0; ks < 4; ks++) {
        uint32_t a0[4], a1[4];
        ldmx4(a0, aOff0 + ks * 32);
        ldmx4(a1, aOff1 + ks * 32);
#pragma unroll
        for (int nt2 = 0; nt2 < 8; nt2++) {
            uint32_t t[4];
            ldmx4(t, bOff + (uint32_t)(nt2 * 16 * FA_PITCH) + ks * 32);
            mma_f16(acc[0][2 * nt2],     a0[0], a0[1], a0[2], a0[3], t[0], t[1]);
            mma_f16(acc[0][2 * nt2 + 1], a0[0], a0[1], a0[2], a0[3], t[2], t[3]);
            mma_f16(acc[1][2 * nt2],     a1[0], a1[1], a1[2], a1[3], t[0], t[1]);
            mma_f16(acc[1][2 * nt2 + 1], a1[0], a1[1], a1[2], a1[3], t[2], t[3]);
        }
    }
    __syncthreads();

    // ---- start V load into the same buffer ----
#pragma unroll
    for (int i = 0; i < 32; i++) {
        const int idx = i * 256 + tid;
        const int r = idx >> 3, s = idx & 7;
        cpa16(kvB + (uint32_t)(r * FA_PITCH + s * 16), Vb + (long)r * 2048 + s * 8);
    }
    asm volatile("cp.async.commit_group;");

    // ---- scale ----
#pragma unroll
    for (int mt = 0; mt < 2; mt++)
#pragma unroll
        for (int nt = 0; nt < 16; nt++)
#pragma unroll
            for (int r = 0; r < 4; r++) acc[mt][nt][r] *= 0.125f;

    // ---- softmax1: row max ----
    float rmax[2][2];
#pragma unroll
    for (int mt = 0; mt < 2; mt++) {
        float lo = -1e30f, hi = -1e30f;
#pragma unroll
        for (int nt = 0; nt < 16; nt++) {
            lo = fmaxf(lo, fmaxf(acc[mt][nt][0], acc[mt][nt][1]));
            hi = fmaxf(hi, fmaxf(acc[mt][nt][2], acc[mt][nt][3]));
        }
        lo = fmaxf(lo, __shfl_xor_sync(~0u, lo, 1)); lo = fmaxf(lo, __shfl_xor_sync(~0u, lo, 2));
        hi = fmaxf(hi, __shfl_xor_sync(~0u, hi, 1)); hi = fmaxf(hi, __shfl_xor_sync(~0u, hi, 2));
        rmax[mt][0] = lo; rmax[mt][1] = hi;
    }
    if (tg == 0) {
        redm[w * 32 + g]      = rmax[0][0];
        redm[w * 32 + 8 + g]  = rmax[0][1];
        redm[w * 32 + 16 + g] = rmax[1][0];
        redm[w * 32 + 24 + g] = rmax[1][1];
    }
    __syncthreads();
    if (tid < 32) {
        float m = -1e30f;
#pragma unroll
        for (int ww = 0; ww < 8; ww++) m = fmaxf(m, redm[ww * 32 + tid]);
        redf[tid] = m;
    }
    __syncthreads();
    rmax[0][0] = redf[g]; rmax[0][1] = redf[8 + g];
    rmax[1][0] = redf[16 + g]; rmax[1][1] = redf[24 + g];
    __syncthreads();

    // ---- exp + row sum ----
    float rsum[2][2];
#pragma unroll
    for (int mt = 0; mt < 2; mt++) {
        float slo = 0.f, shi = 0.f;
#pragma unroll
        for (int nt = 0; nt < 16; nt++) {
            acc[mt][nt][0] = expf(acc[mt][nt][0] - rmax[mt][0]);
            acc[mt][nt][1] = expf(acc[mt][nt][1] - rmax[mt][0]);
            acc[mt][nt][2] = expf(acc[mt][nt][2] - rmax[mt][1]);
            acc[mt][nt][3] = expf(acc[mt][nt][3] - rmax[mt][1]);
            slo += acc[mt][nt][0] + acc[mt][nt][1];
            shi += acc[mt][nt][2] + acc[mt][nt][3];
        }
        slo += __shfl_xor_sync(~0u, slo, 1); slo += __shfl_xor_sync(~0u, slo, 2);
        shi += __shfl_xor_sync(~0u, shi, 1); shi += __shfl_xor_sync(~0u, shi, 2);
        rsum[mt][0] = slo; rsum[mt][1] = shi;
    }
    if (tg == 0) {
        redm[w * 32 + g]      = rsum[0][0];
        redm[w * 32 + 8 + g]  = rsum[0][1];
        redm[w * 32 + 16 + g] = rsum[1][0];
        redm[w * 32 + 24 + g] = rsum[1][1];
    }
    __syncthreads();
    if (tid < 32) {
        float s = 0.f;
#pragma unroll
        for (int ww = 0; ww < 8; ww++) s += redm[ww * 32 + tid];
        redf[tid] = s;
    }
    __syncthreads();
    float inv1[2][2];
    inv1[0][0] = 1.f / redf[g]; inv1[0][1] = 1.f / redf[8 + g];
    inv1[1][0] = 1.f / redf[16 + g]; inv1[1][1] = 1.f / redf[24 + g];
    __syncthreads();

    // ---- attn, mask, write masked ----
    const float alpha = *alphap;
#pragma unroll
    for (int mt = 0; mt < 2; mt++) {
        float* m0p = maskedG + (long)z * TQ_ * TK_
                   + (long)(m0 + mt * 16 + g) * 1024 + w * 128 + 2 * tg;
        float* m1p = m0p + 8L * 1024;
#pragma unroll
        for (int nt = 0; nt < 16; nt++) {
            float a0 = acc[mt][nt][0] * inv1[mt][0]; if (a0 < alpha) a0 = 0.f;
            float a1 = acc[mt][nt][1] * inv1[mt][0]; if (a1 < alpha) a1 = 0.f;
            float a2 = acc[mt][nt][2] * inv1[mt][1]; if (a2 < alpha) a2 = 0.f;
            float a3 = acc[mt][nt][3] * inv1[mt][1]; if (a3 < alpha) a3 = 0.f;
            *reinterpret_cast<float2*>(m0p + nt * 8) = make_float2(a0, a1);
            *reinterpret_cast<float2*>(m1p + nt * 8) = make_float2(a2, a3);
            acc[mt][nt][0] = a0; acc[mt][nt][1] = a1; acc[mt][nt][2] = a2; acc[mt][nt][3] = a3;
        }
    }

    // ---- softmax2: max ----
#pragma unroll
    for (int mt = 0; mt < 2; mt++) {
        float lo = -1e30f, hi = -1e30f;
#pragma unroll
        for (int nt = 0; nt < 16; nt++) {
            lo = fmaxf(lo, fmaxf(acc[mt][nt][0], acc[mt][nt][1]));
            hi = fmaxf(hi, fmaxf(acc[mt][nt][2], acc[mt][nt][3]));
        }
        lo = fmaxf(lo, __shfl_xor_sync(~0u, lo, 1)); lo = fmaxf(lo, __shfl_xor_sync(~0u, lo, 2));
        hi = fmaxf(hi, __shfl_xor_sync(~0u, hi, 1)); hi = fmaxf(hi, __shfl_xor_sync(~0u, hi, 2));
        rmax[mt][0] = lo; rmax[mt][1] = hi;
    }
    if (tg == 0) {
        redm[w * 32 + g]      = rmax[0][0];
        redm[w * 32 + 8 + g]  = rmax[0][1];
        redm[w * 32 + 16 + g] = rmax[1][0];
        redm[w * 32 + 24 + g] = rmax[1][1];
    }
    __syncthreads();
    if (tid < 32) {
        float m = -1e30f;
#pragma unroll
        for (int ww = 0; ww < 8; ww++) m = fmaxf(m, redm[ww * 32 + tid]);
        redf[tid] = m;
    }
    __syncthreads();
    rmax[0][0] = redf[g]; rmax[0][1] = redf[8 + g];
    rmax[1][0] = redf[16 + g]; rmax[1][1] = redf[24 + g];
    __syncthreads();

    // ---- softmax2: exp + sum ----
#pragma unroll
    for (int mt = 0; mt < 2; mt++) {
        float slo = 0.f, shi = 0.f;
#pragma unroll
        for (int nt = 0; nt < 16; nt++) {
            acc[mt][nt][0] = expf(acc[mt][nt][0] - rmax[mt][0]);
            acc[mt][nt][1] = expf(acc[mt][nt][1] - rmax[mt][0]);
            acc[mt][nt][2] = expf(acc[mt][nt][2] - rmax[mt][1]);
            acc[mt][nt][3] = expf(acc[mt][nt][3] - rmax[mt][1]);
            slo += acc[mt][nt][0] + acc[mt][nt][1];
            shi += acc[mt][nt][2] + acc[mt][nt][3];
        }
        slo += __shfl_xor_sync(~0u, slo, 1); slo += __shfl_xor_sync(~0u, slo, 2);
        shi += __shfl_xor_sync(~0u, shi, 1); shi += __shfl_xor_sync(~0u, shi, 2);
        rsum[mt][0] = slo; rsum[mt][1] = shi;
    }
    if (tg == 0) {
        redm[w * 32 + g]      = rsum[0][0];
        redm[w * 32 + 8 + g]  = rsum[0][1];
        redm[w * 32 + 16 + g] = rsum[1][0];
        redm[w * 32 + 24 + g] = rsum[1][1];
    }
    __syncthreads();
    if (tid < 32) {
        float s = 0.f;
#pragma unroll
        for (int ww = 0; ww < 8; ww++) s += redm[ww * 32 + tid];
        redf[tid] = s;
    }
    __syncthreads();
    float inv2[2][2];
    inv2[0][0] = 1.f / redf[g]; inv2[0][1] = 1.f / redf[8 + g];
    inv2[1][0] = 1.f / redf[16 + g]; inv2[1][1] = 1.f / redf[24 + g];

    // ---- pack P to half2 ----
    uint32_t pk[2][16][2];
#pragma unroll
    for (int mt = 0; mt < 2; mt++)
#pragma unroll
        for (int nt = 0; nt < 16; nt++) {
            pk[mt][nt][0] = packh2(acc[mt][nt][0] * inv2[mt][0],
                                   acc[mt][nt][1] * inv2[mt][0]);
            pk[mt][nt][1] = packh2(acc[mt][nt][2] * inv2[mt][1],
                                   acc[mt][nt][3] * inv2[mt][1]);
        }

    // ---- wait for V, then P@V ----
    asm volatile("cp.async.wait_group 0;");
    __syncthreads();

    float o[2][8][4];
#pragma unroll
    for (int mt = 0; mt < 2; mt++)
#pragma unroll
        for (int nt = 0; nt < 8; nt++)
#pragma unroll
            for (int r = 0; r < 4; r++) o[mt][nt][r] = 0.f;

    const uint32_t vOff = kvB + (uint32_t)(((lane & 7) + ((lane >> 3) & 1) * 8) * FA_PITCH
                                           + (lane >> 4) * 16);
#pragma unroll
    for (int s = 0; s < 8; s++) {
        const uint32_t vRow = vOff + (uint32_t)((w * 128 + s * 16) * FA_PITCH);
#pragma unroll
        for (int p = 0; p < 4; p++) {
            uint32_t t[4];
            ldmx4t(t, vRow + p * 32);
#pragma unroll
            for (int mt = 0; mt < 2; mt++) {
                mma_f16(o[mt][2 * p],     pk[mt][2 * s][0], pk[mt][2 * s][1],
                        pk[mt][2 * s + 1][0], pk[mt][2 * s + 1][1], t[0], t[1]);
                mma_f16(o[mt][2 * p + 1], pk[mt][2 * s][0], pk[mt][2 * s][1],
                        pk[mt][2 * s + 1][0], pk[mt][2 * s + 1][1], t[2], t[3]);
            }
        }
    }

    // ---- cross-warp O reduce via smem ----
#pragma unroll
    for (int mt = 0; mt < 2; mt++)
#pragma unroll
        for (int nt = 0; nt < 8; nt++) {
            const int c = nt * 8 + 2 * tg;
            const int r0 = mt * 16 + g, r1 = mt * 16 + 8 + g;
            Ored[w * FA_OWARP + r0 * FA_OROW + c]     = o[mt][nt][0];
            Ored[w * FA_OWARP + r0 * FA_OROW + c + 1] = o[mt][nt][1];
            Ored[w * FA_OWARP + r1 * FA_OROW + c]     = o[mt][nt][2];
            Ored[w * FA_OWARP + r1 * FA_OROW + c + 1] = o[mt][nt][3];
        }
    __syncthreads();
    {
        const int e = tid * 8;
        const int r = e >> 6, c = e & 63;
        float s[8];
#pragma unroll
        for (int j = 0; j < 8; j++) s[j] = 0.f;
#pragma unroll
        for (int ww = 0; ww < 8; ww++) {
            const float* p = &Ored[ww * FA_OWARP + r * FA_OROW + c];
#pragma unroll
            for (int j = 0; j < 8; j++) s[j] += p[j];
        }
        __half2* op = reinterpret_cast<__half2*>(
            Og + zb * (long)(TQ_ * D_) + (long)(m0 + r) * D_ + zh * HD_ + c);
#pragma unroll
        for (int j = 0; j < 4; j++)
            op[j] = __floats2half2_rn(s[2 * j], s[2 * j + 1]);
    }
}

// ---------------- LayerNorm(a + b) * g + beta ------------------------------------
__global__ void __launch_bounds__(256)
add_ln_k(const float* __restrict__ A, const float* __restrict__ Bsrc,
         const float* __restrict__ g, const float* __restrict__ bet,
         float* __restrict__ outF, __half* __restrict__ outH)
{
    __shared__ float red[32];
    const long row = blockIdx.x;
    const int tid = threadIdx.x;

    float4 a4 = reinterpret_cast<const float4*>(A    + row * 1024)[tid];
    float4 b4 = reinterpret_cast<const float4*>(Bsrc + row * 1024)[tid];
    float x[4] = {a4.x + b4.x, a4.y + b4.y, a4.z + b4.z, a4.w + b4.w};

    float s = x[0] + x[1] + x[2] + x[3];
    s = blockRedSum(s, red);
    const float mu = s * (1.f / 1024.f);

    float vs = 0.f;
#pragma unroll
    for (int i = 0; i < 4; i++) { float d = x[i] - mu; vs += d * d; }
    vs = blockRedSum(vs, red);
    const float inv = rsqrtf(vs * (1.f / 1024.f) + 1e-5f);

    float4 g4 = reinterpret_cast<const float4*>(g)[tid];
    float4 e4 = reinterpret_cast<const float4*>(bet)[tid];
    float o[4];
    o[0] = (x[0] - mu) * inv * g4.x + e4.x;
    o[1] = (x[1] - mu) * inv * g4.y + e4.y;
    o[2] = (x[2] - mu) * inv * g4.z + e4.z;
    o[3] = (x[3] - mu) * inv * g4.w + e4.w;

    if (outF)
        reinterpret_cast<float4*>(outF + row * 1024)[tid] =
            make_float4(o[0], o[1], o[2], o[3]);
    if (outH) {
        __half2* oh = reinterpret_cast<__half2*>(outH + row * 1024);
        oh[2 * tid]     = __floats2half2_rn(o[0], o[1]);
        oh[2 * tid + 1] = __floats2half2_rn(o[2], o[3]);
    }
}

// ---------------- driver ---------------------------------------------------------
extern "C" void kernel_launch(void* const* d_in, const int* in_sizes, int n_in,
                              void* d_out, int out_size)
{
    const float* base   = (const float*)d_in[0];
    const float* fusion = (const float*)d_in[1];
    const float* Wq     = (const float*)d_in[2];
    const float* Wk     = (const float*)d_in[3];
    const float* Wv     = (const float*)d_in[4];
    const float* Wo     = (const float*)d_in[5];
    const float* g1     = (const float*)d_in[6];
    const float* b1     = (const float*)d_in[7];
    const float* g2     = (const float*)d_in[8];
    const float* b2     = (const float*)d_in[9];
    const float* fc1_w  = (const float*)d_in[10];
    const float* fc1_b  = (const float*)d_in[11];
    const float* fc2_w  = (const float*)d_in[12];
    const float* fc2_b  = (const float*)d_in[13];
    const float* rw     = (const float*)d_in[14];
    const float* rbias  = (const float*)d_in[15];
    const float* alphap = (const float*)d_in[16];

    float* outf = (float*)d_out;
    float* outm = outf + (long)B_ * TQ_ * D_;

    __half *baseh, *fush, *qh, *kvh, *aoh, *xh, *h1h, *yh, *wh;
    float *x, *wo, *ff;
    cudaGetSymbolAddress((void**)&baseh, g_baseh);
    cudaGetSymbolAddress((void**)&fush,  g_fush);
    cudaGetSymbolAddress((void**)&qh,   g_qh);
    cudaGetSymbolAddress((void**)&kvh,  g_kvh);
    cudaGetSymbolAddress((void**)&aoh,  g_aoh);
    cudaGetSymbolAddress((void**)&xh,   g_xh);
    cudaGetSymbolAddress((void**)&h1h,  g_h1h);
    cudaGetSymbolAddress((void**)&yh,   g_yh);
    cudaGetSymbolAddress((void**)&wh,   g_wh);
    cudaGetSymbolAddress((void**)&x,    g_x);
    cudaGetSymbolAddress((void**)&wo,   g_wo);
    cudaGetSymbolAddress((void**)&ff,   g_ff);

    cudaFuncSetAttribute(gemm_h,
                         cudaFuncAttributeMaxDynamicSharedMemorySize, GEMMH_SMEM);
    cudaFuncSetAttribute(fattn_k,
                         cudaFuncAttributeMaxDynamicSharedMemorySize, FA_SMEM);

    const dim3 blk(256);
    const dim3 gBig(D_ / 128, (B_ * TQ_) / 128, 1);
    const dim3 gKV(2048 / 128, (B_ * TK_) / 128, 1);
    const long WN = 1024 * 1024;
    const int act4 = (B_ * TQ_ * D_) / 4;
    const int RB = 256;

    conv_h_k<<<(act4 + RB - 1) / RB, RB>>>(base,   baseh, act4);
    conv_h_k<<<(act4 + RB - 1) / RB, RB>>>(fusion, fush,  act4);
    conv_w_k<<<7 * 262144 / RB, RB>>>(Wq, Wk, Wv, Wo, fc1_w, fc2_w, rw, wh);
    const __half *WqH = wh, *WkH = wh + WN, *WoH = wh + 3*WN,
                 *f1H = wh + 4*WN, *f2H = wh + 5*WN, *rwH = wh + 6*WN;

    // Q projection (fp16 out)
    gemm_h<<<gBig, blk, GEMMH_SMEM>>>(baseh, WqH, qh, D_, D_, D_, D_, 1.f, nullptr, 8);
    // K+V fused projection (Wk|Wv contiguous), C row stride 2048
    gemm_h<<<gKV, blk, GEMMH_SMEM>>>(fush, WkH, kvh, D_, D_, D_, 2048, 1.f, nullptr, 8);

    // fused attention: masked (fp32) + ao (fp16)
    fattn_k<<<dim3(TQ_ / 32, B_ * H_), blk, FA_SMEM>>>(qh, kvh, outm, aoh, alphap);

    // O projection (fp32 out -> LN1)
    gemm_h<<<gBig, blk, GEMMH_SMEM>>>(aoh, WoH, wo, D_, D_, D_, D_, 1.f, nullptr, 0);

    // x = LN(base + wo): fp32 -> x, fp16 -> xh
    add_ln_k<<<B_ * TQ_, blk>>>(base, wo, g1, b1, x, xh);

    // FFN
    gemm_h<<<gBig, blk, GEMMH_SMEM>>>(xh,  f1H, h1h, D_, D_, D_, D_, 1.f, fc1_b, 11);
    gemm_h<<<gBig, blk, GEMMH_SMEM>>>(h1h, f2H, ff,  D_, D_, D_, D_, 1.f, fc2_b, 3);

    // y = LN(x + ff): fp16 -> yh
    add_ln_k<<<B_ * TQ_, blk>>>(x, ff, g2, b2, nullptr, yh);

    // final = y rw^T + rb (fp32 out)
    gemm_h<<<gBig, blk, GEMMH_SMEM>>>(yh, rwH, outf, D_, D_, D_, D_, 1.f, rbias, 1);
}